// round 1
// baseline (speedup 1.0000x reference)
#include <cuda_runtime.h>
#include <cuda_bf16.h>
#include <cstdint>

// Problem constants
#define BB   16
#define LL   1024
#define HID  1024
#define HH   16
#define EE   64
#define NROW (BB * HID)          // 16384 rows of (B,HID,L) layouts
#define NF   308                 // freq bins 205..512
#define F0   205
#define TOPK 6

// ---------------- scratch (device globals; no allocation allowed) -----------
__device__ float  g_q[NROW * LL];        // (B,HID,L): q[b,h,e,t]
__device__ float  g_k[NROW * LL];
__device__ float  g_v[NROW * LL];
__device__ float  g_ctx[NROW * LL];      // (B,HID,L) delays_agg
__device__ float  g_hidden[NROW * LL];   // (B*L, HID) row-major
__device__ float2 g_P[NROW * NF];        // per-row cross-spectrum (staging)
__device__ float2 g_S[BB][NF];           // channel-summed cross-spectrum
__device__ float  g_mv[BB][LL];          // mean_value
__device__ int    g_idx[TOPK];
__device__ float  g_tc[BB][TOPK];        // softmax weights

// ---------------- GEMM 1: x @ W + b, scatter to (B,HID,L) ------------------
// C[m,n] = sum_k X[m,k] * W[k,n];  m = b*L + t;  out[(b*HID+n)*L + t]
__global__ void __launch_bounds__(256) gemm_qkv_kernel(
    const float* __restrict__ X, const float* __restrict__ W,
    const float* __restrict__ bias, int which)
{
    __shared__ float As[8][128];
    __shared__ float Bs[8][128];
    float* Out = (which == 0) ? g_q : (which == 1) ? g_k : g_v;

    const int m0 = blockIdx.y * 128;
    const int n0 = blockIdx.x * 128;
    const int tid = threadIdx.x;

    const int a_m = tid >> 1;            // 0..127
    const int a_k = (tid & 1) * 4;       // 0 or 4
    const int b_k = tid >> 5;            // 0..7
    const int b_n = (tid & 31) * 4;      // 0..124
    const int tm = (tid >> 4) * 8;
    const int tn = (tid & 15) * 8;

    float acc[8][8];
    #pragma unroll
    for (int i = 0; i < 8; i++)
        #pragma unroll
        for (int j = 0; j < 8; j++) acc[i][j] = 0.f;

    for (int k0 = 0; k0 < 1024; k0 += 8) {
        float4 av = *(const float4*)&X[(m0 + a_m) * 1024 + k0 + a_k];
        As[a_k + 0][a_m] = av.x; As[a_k + 1][a_m] = av.y;
        As[a_k + 2][a_m] = av.z; As[a_k + 3][a_m] = av.w;
        float4 bv = *(const float4*)&W[(k0 + b_k) * 1024 + n0 + b_n];
        *(float4*)&Bs[b_k][b_n] = bv;
        __syncthreads();
        #pragma unroll
        for (int kk = 0; kk < 8; kk++) {
            float4 a0 = *(float4*)&As[kk][tm];
            float4 a1 = *(float4*)&As[kk][tm + 4];
            float4 b0 = *(float4*)&Bs[kk][tn];
            float4 b1 = *(float4*)&Bs[kk][tn + 4];
            float a[8] = {a0.x, a0.y, a0.z, a0.w, a1.x, a1.y, a1.z, a1.w};
            float b[8] = {b0.x, b0.y, b0.z, b0.w, b1.x, b1.y, b1.z, b1.w};
            #pragma unroll
            for (int i = 0; i < 8; i++)
                #pragma unroll
                for (int j = 0; j < 8; j++) acc[i][j] += a[i] * b[j];
        }
        __syncthreads();
    }
    #pragma unroll
    for (int i = 0; i < 8; i++) {
        int m = m0 + tm + i;
        int b = m >> 10, t = m & 1023;
        #pragma unroll
        for (int j = 0; j < 8; j++) {
            int n = n0 + tn + j;
            Out[((b << 10) + n) * 1024 + t] = acc[i][j] + bias[n];
        }
    }
}

// ---------------- GEMM 2: ctx(B,HID,L) @ Wd + bd -> hidden (B*L,HID) -------
__global__ void __launch_bounds__(256) gemm_d_kernel(
    const float* __restrict__ W, const float* __restrict__ bias)
{
    __shared__ float As[8][128];
    __shared__ float Bs[8][128];

    const int m0 = blockIdx.y * 128;
    const int n0 = blockIdx.x * 128;
    const int tid = threadIdx.x;
    const int b0 = m0 >> 10;
    const int t0 = m0 & 1023;

    const int a_k = tid >> 5;            // 0..7
    const int a_m = (tid & 31) * 4;      // 0..124
    const int b_k = tid >> 5;
    const int b_n = (tid & 31) * 4;
    const int tm = (tid >> 4) * 8;
    const int tn = (tid & 15) * 8;

    float acc[8][8];
    #pragma unroll
    for (int i = 0; i < 8; i++)
        #pragma unroll
        for (int j = 0; j < 8; j++) acc[i][j] = 0.f;

    for (int k0 = 0; k0 < 1024; k0 += 8) {
        float4 av = *(const float4*)&g_ctx[((b0 << 10) + k0 + a_k) * 1024 + t0 + a_m];
        *(float4*)&As[a_k][a_m] = av;
        float4 bv = *(const float4*)&W[(k0 + b_k) * 1024 + n0 + b_n];
        *(float4*)&Bs[b_k][b_n] = bv;
        __syncthreads();
        #pragma unroll
        for (int kk = 0; kk < 8; kk++) {
            float4 a0 = *(float4*)&As[kk][tm];
            float4 a1 = *(float4*)&As[kk][tm + 4];
            float4 b0 = *(float4*)&Bs[kk][tn];
            float4 b1 = *(float4*)&Bs[kk][tn + 4];
            float a[8] = {a0.x, a0.y, a0.z, a0.w, a1.x, a1.y, a1.z, a1.w};
            float b[8] = {b0.x, b0.y, b0.z, b0.w, b1.x, b1.y, b1.z, b1.w};
            #pragma unroll
            for (int i = 0; i < 8; i++)
                #pragma unroll
                for (int j = 0; j < 8; j++) acc[i][j] += a[i] * b[j];
        }
        __syncthreads();
    }
    #pragma unroll
    for (int i = 0; i < 8; i++) {
        int m = m0 + tm + i;
        #pragma unroll
        for (int j = 0; j < 8; j++) {
            int n = n0 + tn + j;
            g_hidden[m * 1024 + n] = acc[i][j] + bias[n];
        }
    }
}

// ---------------- FFT + cross spectrum per (b,h,e) row ----------------------
// z = q + i*k; one 1024-pt complex FFT; Q(f)=(A+B̄)/2, K(f)=(A-B̄)/(2i),
// P(f)=Q*conj(K) = (i/4)*(A+B̄)*conj(A-B̄), B̄ = conj(Z[1024-f]).
__global__ void __launch_bounds__(256) fft_corr_kernel()
{
    __shared__ float2 Z[1024];
    __shared__ float2 Wt[512];
    const int row = blockIdx.x;
    const int tid = threadIdx.x;
    const float* qr = g_q + (size_t)row * 1024;
    const float* kr = g_k + (size_t)row * 1024;

    for (int j = tid; j < 512; j += 256) {
        float s, c;
        sincospif(-(float)j / 512.0f, &s, &c);   // e^{-2*pi*i*j/1024}
        Wt[j] = make_float2(c, s);
    }
    for (int t = tid; t < 1024; t += 256) {
        int r = __brev((unsigned)t) >> 22;       // 10-bit reversal
        Z[r] = make_float2(qr[t], kr[t]);
    }
    __syncthreads();

    #pragma unroll
    for (int s = 0; s < 10; s++) {
        const int half = 1 << s;
        for (int i = tid; i < 512; i += 256) {
            int j = i & (half - 1);
            int p1 = ((i >> s) << (s + 1)) + j;
            int p2 = p1 + half;
            float2 w = Wt[j << (9 - s)];
            float2 z2 = Z[p2], z1 = Z[p1];
            float tr = z2.x * w.x - z2.y * w.y;
            float ti = z2.x * w.y + z2.y * w.x;
            Z[p2] = make_float2(z1.x - tr, z1.y - ti);
            Z[p1] = make_float2(z1.x + tr, z1.y + ti);
        }
        __syncthreads();
    }

    for (int f = F0 + tid; f <= 512; f += 256) {
        float2 A  = Z[f];
        float2 Zc = Z[1024 - f];
        float Br =  Zc.x, Bi = -Zc.y;
        float Ur = A.x + Br, Ui = A.y + Bi;
        float Vr = A.x - Br, Vi = A.y - Bi;
        float Pr = 0.25f * (Ur * Vi - Ui * Vr);
        float Pi = 0.25f * (Ur * Vr + Ui * Vi);
        g_P[(size_t)row * NF + (f - F0)] = make_float2(Pr, Pi);
    }
}

// ---------------- deterministic channel reduction: S[b][f] = sum_{h,e} P ---
__global__ void __launch_bounds__(256) reduce_S_kernel()
{
    const int b = blockIdx.x, j = blockIdx.y;
    const int tid = threadIdx.x;
    float2 acc = make_float2(0.f, 0.f);
    for (int r = tid; r < 1024; r += 256) {
        float2 p = g_P[(size_t)((b << 10) + r) * NF + j];
        acc.x += p.x; acc.y += p.y;
    }
    __shared__ float2 sh[256];
    sh[tid] = acc;
    __syncthreads();
    for (int o = 128; o > 0; o >>= 1) {
        if (tid < o) { sh[tid].x += sh[tid + o].x; sh[tid].y += sh[tid + o].y; }
        __syncthreads();
    }
    if (tid == 0) g_S[b][j] = sh[0];
}

// ---------------- irfft of masked spectrum -> mean_value --------------------
// mv[b,tau] = (1/(1024*1024)) * [ 2*sum_{f=205..511} Re(S e^{+i 2pi f tau/N})
//                                 +   Re(S_512 e^{+i pi tau}) ]
__global__ void __launch_bounds__(256) irfft_mean_kernel()
{
    __shared__ float2 tw[1024];
    __shared__ float2 Sb[NF];
    const int b = blockIdx.x;
    const int tid = threadIdx.x;
    for (int j = tid; j < 1024; j += 256) {
        float s, c;
        sincospif((float)j / 512.0f, &s, &c);    // e^{+2*pi*i*j/1024}
        tw[j] = make_float2(c, s);
    }
    for (int j = tid; j < NF; j += 256) Sb[j] = g_S[b][j];
    __syncthreads();

    const int tau = blockIdx.y * 256 + tid;
    float acc = 0.f;
    #pragma unroll 4
    for (int j = 0; j < NF - 1; j++) {
        int id = ((F0 + j) * tau) & 1023;
        float2 s = Sb[j], w = tw[id];
        acc += s.x * w.x - s.y * w.y;
    }
    acc *= 2.0f;
    {
        int id = (512 * tau) & 1023;             // sin is exactly 0 here
        float2 s = Sb[NF - 1], w = tw[id];
        acc += s.x * w.x - s.y * w.y;
    }
    g_mv[b][tau] = acc * (1.0f / (1024.0f * 1024.0f));
}

// ---------------- global top-6 lags + per-batch softmax ---------------------
__global__ void __launch_bounds__(256) topk_kernel()
{
    __shared__ float g[1024];
    __shared__ float rv[256];
    __shared__ int   ri[256];
    __shared__ int   chosen[TOPK];
    const int tid = threadIdx.x;

    for (int t = tid; t < 1024; t += 256) {
        float s = 0.f;
        #pragma unroll
        for (int b = 0; b < BB; b++) s += g_mv[b][t];
        g[t] = s;
    }
    __syncthreads();

    for (int p = 0; p < TOPK; p++) {
        float best = -3.0e38f; int bi = 1 << 30;
        for (int t = tid; t < 1024; t += 256) {
            float v = g[t];
            if (v > best) { best = v; bi = t; }   // ascending t -> first max kept
        }
        rv[tid] = best; ri[tid] = bi;
        __syncthreads();
        for (int o = 128; o > 0; o >>= 1) {
            if (tid < o) {
                float v2 = rv[tid + o]; int i2 = ri[tid + o];
                if (v2 > rv[tid] || (v2 == rv[tid] && i2 < ri[tid])) {
                    rv[tid] = v2; ri[tid] = i2;
                }
            }
            __syncthreads();
        }
        if (tid == 0) { chosen[p] = ri[0]; g[ri[0]] = -3.0e38f; }
        __syncthreads();
    }

    if (tid < BB) {
        int b = tid;
        float w[TOPK], mx = -3.0e38f;
        #pragma unroll
        for (int i = 0; i < TOPK; i++) { w[i] = g_mv[b][chosen[i]]; mx = fmaxf(mx, w[i]); }
        float sum = 0.f;
        #pragma unroll
        for (int i = 0; i < TOPK; i++) { w[i] = expf(w[i] - mx); sum += w[i]; }
        #pragma unroll
        for (int i = 0; i < TOPK; i++) g_tc[b][i] = w[i] / sum;
    }
    if (tid >= 32 && tid < 32 + TOPK) g_idx[tid - 32] = chosen[tid - 32];
}

// ---------------- weighted circular-shift aggregation of v ------------------
__global__ void __launch_bounds__(256) gather_kernel()
{
    __shared__ float vs[1024];
    __shared__ int   sh[TOPK];
    __shared__ float w[TOPK];
    const int row = blockIdx.x;       // b*HID + c
    const int b = row >> 10;
    const int tid = threadIdx.x;
    for (int t = tid; t < 1024; t += 256) vs[t] = g_v[(size_t)row * 1024 + t];
    if (tid < TOPK) { sh[tid] = g_idx[tid]; w[tid] = g_tc[b][tid]; }
    __syncthreads();
    for (int t = tid; t < 1024; t += 256) {
        float a = 0.f;
        #pragma unroll
        for (int i = 0; i < TOPK; i++) a += w[i] * vs[(t + sh[i]) & 1023];
        g_ctx[(size_t)row * 1024 + t] = a;
    }
}

// ---------------- residual + LayerNorm --------------------------------------
__global__ void __launch_bounds__(256) ln_kernel(
    const float* __restrict__ x, const float* __restrict__ gamma,
    const float* __restrict__ beta, float* __restrict__ out)
{
    const int m = blockIdx.x;
    const int tid = threadIdx.x;
    const float* h  = g_hidden + (size_t)m * 1024;
    const float* xi = x        + (size_t)m * 1024;

    float v[4];
    float s1 = 0.f, s2 = 0.f;
    #pragma unroll
    for (int i = 0; i < 4; i++) {
        float t = h[tid + 256 * i] + xi[tid + 256 * i];
        v[i] = t; s1 += t; s2 += t * t;
    }
    #pragma unroll
    for (int o = 16; o > 0; o >>= 1) {
        s1 += __shfl_xor_sync(0xffffffffu, s1, o);
        s2 += __shfl_xor_sync(0xffffffffu, s2, o);
    }
    __shared__ float w1[8], w2[8];
    __shared__ float sh_mean, sh_inv;
    const int wid = tid >> 5, lane = tid & 31;
    if (lane == 0) { w1[wid] = s1; w2[wid] = s2; }
    __syncthreads();
    if (tid == 0) {
        float a = 0.f, bq = 0.f;
        #pragma unroll
        for (int i = 0; i < 8; i++) { a += w1[i]; bq += w2[i]; }
        float mean = a * (1.0f / 1024.0f);
        float var  = bq * (1.0f / 1024.0f) - mean * mean;
        sh_mean = mean;
        sh_inv  = rsqrtf(var + 1e-12f);
    }
    __syncthreads();
    const float mean = sh_mean, inv = sh_inv;
    #pragma unroll
    for (int i = 0; i < 4; i++) {
        int c = tid + 256 * i;
        out[(size_t)m * 1024 + c] = (v[i] - mean) * inv * gamma[c] + beta[c];
    }
}

// ---------------- launch ----------------------------------------------------
extern "C" void kernel_launch(void* const* d_in, const int* in_sizes, int n_in,
                              void* d_out, int out_size)
{
    (void)in_sizes; (void)n_in; (void)out_size;
    const float* x     = (const float*)d_in[0];
    const float* Wq    = (const float*)d_in[2];
    const float* bq    = (const float*)d_in[3];
    const float* Wk    = (const float*)d_in[4];
    const float* bk    = (const float*)d_in[5];
    const float* Wv    = (const float*)d_in[6];
    const float* bv    = (const float*)d_in[7];
    const float* Wd    = (const float*)d_in[8];
    const float* bd    = (const float*)d_in[9];
    const float* gamma = (const float*)d_in[10];
    const float* beta  = (const float*)d_in[11];
    float* out = (float*)d_out;

    dim3 ggrid(8, 128);   // N/128 x M/128
    gemm_qkv_kernel<<<ggrid, 256>>>(x, Wq, bq, 0);
    gemm_qkv_kernel<<<ggrid, 256>>>(x, Wk, bk, 1);
    gemm_qkv_kernel<<<ggrid, 256>>>(x, Wv, bv, 2);
    fft_corr_kernel<<<NROW, 256>>>();
    reduce_S_kernel<<<dim3(BB, NF), 256>>>();
    irfft_mean_kernel<<<dim3(BB, 4), 256>>>();
    topk_kernel<<<1, 256>>>();
    gather_kernel<<<NROW, 256>>>();
    gemm_d_kernel<<<ggrid, 256>>>(Wd, bd);
    ln_kernel<<<NROW, 256>>>(x, gamma, beta, out);
}

// round 4
// speedup vs baseline: 1.5071x; 1.5071x over previous
#include <cuda_runtime.h>
#include <cuda_bf16.h>
#include <cstdint>

// Problem constants
#define BB   16
#define LL   1024
#define HID  1024
#define NROW (BB * HID)          // 16384 rows of (B,HID,L) layouts
#define NF   308                 // freq bins 205..512
#define F0   205
#define TOPK 6

// ---------------- scratch (device globals; no allocation allowed) -----------
__device__ float  g_q[NROW * LL];        // (B,HID,L): q[b,h,e,t]
__device__ float  g_k[NROW * LL];
__device__ float  g_v[NROW * LL];
__device__ float  g_ctx[NROW * LL];      // (B,HID,L) delays_agg
__device__ float  g_hidden[NROW * LL];   // (B*L, HID) row-major
__device__ float2 g_P[NROW * NF];        // per-row cross-spectrum (staging)
__device__ float2 g_S[BB][NF];           // channel-summed cross-spectrum
__device__ float  g_mv[BB][LL];          // mean_value
__device__ int    g_idx[TOPK];
__device__ float  g_tc[BB][TOPK];        // softmax weights

// ---------------- tf32 helpers ----------------------------------------------
__device__ __forceinline__ unsigned f2tf32(float x) {
    unsigned r;
    asm("cvt.rna.tf32.f32 %0, %1;" : "=r"(r) : "f"(x));
    return r;
}
__device__ __forceinline__ void split_tf32(float x, float& hi, float& lo) {
    unsigned h = f2tf32(x);
    float hf = __uint_as_float(h);
    hi = hf;
    lo = __uint_as_float(f2tf32(x - hf));
}
__device__ __forceinline__ void mma_tf32(float* c, const unsigned* a, const unsigned* b) {
    asm volatile(
        "mma.sync.aligned.m16n8k8.row.col.f32.tf32.tf32.f32 "
        "{%0,%1,%2,%3}, {%4,%5,%6,%7}, {%8,%9}, {%0,%1,%2,%3};"
        : "+f"(c[0]), "+f"(c[1]), "+f"(c[2]), "+f"(c[3])
        : "r"(a[0]), "r"(a[1]), "r"(a[2]), "r"(a[3]), "r"(b[0]), "r"(b[1]));
}

// smem strides (floats)
#define AS_STRIDE 36     // 32 + 4 pad: (4m+k)%32 bijective on frag loads
#define BS_STRIDE 136    // 128 + 8 pad: (8k+n)%32 bijective on frag loads
#define AS_FLOATS (128 * AS_STRIDE)      // 4608
#define BS_FLOATS (32 * BS_STRIDE)       // 4352
#define G1_SMEM   ((2 * AS_FLOATS + 2 * BS_FLOATS) * 4)   // 71680 B
#define A2_FLOATS (32 * BS_STRIDE)       // 4352 (transposed layout for GEMM-D)
#define G2_SMEM   ((2 * A2_FLOATS + 2 * BS_FLOATS) * 4)   // 69632 B

// ---------------- GEMM 1: x @ W + b, scatter to (B,HID,L), tf32-split -------
// C[m,n] = sum_k X[m,k]*W[k,n];  m = b*L + t;  out[(b*HID+n)*L + t]
__global__ void __launch_bounds__(256) gemm_qkv_mma(
    const float* __restrict__ X, const float* __restrict__ W,
    const float* __restrict__ bias, int which)
{
    extern __shared__ float smem[];
    float* As_hi = smem;
    float* As_lo = smem + AS_FLOATS;
    float* Bs_hi = smem + 2 * AS_FLOATS;
    float* Bs_lo = smem + 2 * AS_FLOATS + BS_FLOATS;

    float* Out = (which == 0) ? g_q : (which == 1) ? g_k : g_v;

    const int m0 = blockIdx.y * 128;
    const int n0 = blockIdx.x * 128;
    const int tid  = threadIdx.x;
    const int lane = tid & 31;
    const int wid  = tid >> 5;
    const int wm = wid & 1;          // 2 warps along M
    const int wn = wid >> 1;         // 4 warps along N
    const int gid = lane >> 2;
    const int tig = lane & 3;

    float c[4][4][4];
    #pragma unroll
    for (int i = 0; i < 4; i++)
        #pragma unroll
        for (int j = 0; j < 4; j++)
            #pragma unroll
            for (int r = 0; r < 4; r++) c[i][j][r] = 0.f;

    float4 areg[4], breg[4];

    // preload tile 0
    #pragma unroll
    for (int i = 0; i < 4; i++) {
        int idx = tid + i * 256;
        int m = idx >> 3, k4 = idx & 7;
        areg[i] = *(const float4*)&X[(m0 + m) * 1024 + k4 * 4];
        int kb = idx >> 5, n4 = idx & 31;
        breg[i] = *(const float4*)&W[kb * 1024 + n0 + n4 * 4];
    }

    for (int kt = 0; kt < 32; kt++) {
        // split + store current tile
        #pragma unroll
        for (int i = 0; i < 4; i++) {
            int idx = tid + i * 256;
            int m = idx >> 3, k4 = idx & 7;
            float h0, l0, h1, l1, h2, l2, h3, l3;
            split_tf32(areg[i].x, h0, l0); split_tf32(areg[i].y, h1, l1);
            split_tf32(areg[i].z, h2, l2); split_tf32(areg[i].w, h3, l3);
            *(float4*)&As_hi[m * AS_STRIDE + k4 * 4] = make_float4(h0, h1, h2, h3);
            *(float4*)&As_lo[m * AS_STRIDE + k4 * 4] = make_float4(l0, l1, l2, l3);
            int kb = idx >> 5, n4 = idx & 31;
            split_tf32(breg[i].x, h0, l0); split_tf32(breg[i].y, h1, l1);
            split_tf32(breg[i].z, h2, l2); split_tf32(breg[i].w, h3, l3);
            *(float4*)&Bs_hi[kb * BS_STRIDE + n4 * 4] = make_float4(h0, h1, h2, h3);
            *(float4*)&Bs_lo[kb * BS_STRIDE + n4 * 4] = make_float4(l0, l1, l2, l3);
        }
        __syncthreads();

        // prefetch next tile
        if (kt < 31) {
            int kofs = (kt + 1) * 32;
            #pragma unroll
            for (int i = 0; i < 4; i++) {
                int idx = tid + i * 256;
                int m = idx >> 3, k4 = idx & 7;
                areg[i] = *(const float4*)&X[(m0 + m) * 1024 + kofs + k4 * 4];
                int kb = idx >> 5, n4 = idx & 31;
                breg[i] = *(const float4*)&W[(kofs + kb) * 1024 + n0 + n4 * 4];
            }
        }

        // compute 4 k-steps
        #pragma unroll
        for (int ks = 0; ks < 4; ks++) {
            const int kk = ks * 8;
            unsigned ah[4][4], al[4][4], bh[4][2], bl[4][2];
            #pragma unroll
            for (int mi = 0; mi < 4; mi++) {
                int mr = wm * 64 + mi * 16 + gid;
                ah[mi][0] = __float_as_uint(As_hi[mr * AS_STRIDE + kk + tig]);
                ah[mi][1] = __float_as_uint(As_hi[(mr + 8) * AS_STRIDE + kk + tig]);
                ah[mi][2] = __float_as_uint(As_hi[mr * AS_STRIDE + kk + tig + 4]);
                ah[mi][3] = __float_as_uint(As_hi[(mr + 8) * AS_STRIDE + kk + tig + 4]);
                al[mi][0] = __float_as_uint(As_lo[mr * AS_STRIDE + kk + tig]);
                al[mi][1] = __float_as_uint(As_lo[(mr + 8) * AS_STRIDE + kk + tig]);
                al[mi][2] = __float_as_uint(As_lo[mr * AS_STRIDE + kk + tig + 4]);
                al[mi][3] = __float_as_uint(As_lo[(mr + 8) * AS_STRIDE + kk + tig + 4]);
            }
            #pragma unroll
            for (int ni = 0; ni < 4; ni++) {
                int nc = wn * 32 + ni * 8 + gid;
                bh[ni][0] = __float_as_uint(Bs_hi[(kk + tig) * BS_STRIDE + nc]);
                bh[ni][1] = __float_as_uint(Bs_hi[(kk + tig + 4) * BS_STRIDE + nc]);
                bl[ni][0] = __float_as_uint(Bs_lo[(kk + tig) * BS_STRIDE + nc]);
                bl[ni][1] = __float_as_uint(Bs_lo[(kk + tig + 4) * BS_STRIDE + nc]);
            }
            #pragma unroll
            for (int mi = 0; mi < 4; mi++)
                #pragma unroll
                for (int ni = 0; ni < 4; ni++) {
                    mma_tf32(c[mi][ni], ah[mi], bh[ni]);
                    mma_tf32(c[mi][ni], ah[mi], bl[ni]);
                    mma_tf32(c[mi][ni], al[mi], bh[ni]);
                }
        }
        __syncthreads();
    }

    // epilogue: scatter to (b, n, t)
    const int bidx = m0 >> 10;
    #pragma unroll
    for (int mi = 0; mi < 4; mi++) {
        #pragma unroll
        for (int r = 0; r < 2; r++) {
            int m = m0 + wm * 64 + mi * 16 + gid + r * 8;
            int t = m & 1023;
            #pragma unroll
            for (int ni = 0; ni < 4; ni++) {
                int nb = n0 + wn * 32 + ni * 8 + 2 * tig;
                float v0 = c[mi][ni][r * 2 + 0] + bias[nb];
                float v1 = c[mi][ni][r * 2 + 1] + bias[nb + 1];
                Out[(((size_t)(bidx << 10) + nb) << 10) + t] = v0;
                Out[(((size_t)(bidx << 10) + nb + 1) << 10) + t] = v1;
            }
        }
    }
}

// ---------------- GEMM 2: ctx(B,HID,L) @ Wd + bd -> hidden (B*L,HID) --------
__global__ void __launch_bounds__(256) gemm_d_mma(
    const float* __restrict__ W, const float* __restrict__ bias)
{
    extern __shared__ float smem[];
    float* As_hi = smem;                         // [k][t] layout, 32 x 136
    float* As_lo = smem + A2_FLOATS;
    float* Bs_hi = smem + 2 * A2_FLOATS;
    float* Bs_lo = smem + 2 * A2_FLOATS + BS_FLOATS;

    const int m0 = blockIdx.y * 128;
    const int n0 = blockIdx.x * 128;
    const int b0 = m0 >> 10;
    const int t0 = m0 & 1023;
    const int tid  = threadIdx.x;
    const int lane = tid & 31;
    const int wid  = tid >> 5;
    const int wm = wid & 1;
    const int wn = wid >> 1;
    const int gid = lane >> 2;
    const int tig = lane & 3;

    float c[4][4][4];
    #pragma unroll
    for (int i = 0; i < 4; i++)
        #pragma unroll
        for (int j = 0; j < 4; j++)
            #pragma unroll
            for (int r = 0; r < 4; r++) c[i][j][r] = 0.f;

    float4 areg[4], breg[4];
    #pragma unroll
    for (int i = 0; i < 4; i++) {
        int idx = tid + i * 256;
        int kb = idx >> 5, t4 = idx & 31;
        areg[i] = *(const float4*)&g_ctx[(((size_t)(b0 << 10) + kb) << 10) + t0 + t4 * 4];
        breg[i] = *(const float4*)&W[kb * 1024 + n0 + t4 * 4];
    }

    for (int kt = 0; kt < 32; kt++) {
        #pragma unroll
        for (int i = 0; i < 4; i++) {
            int idx = tid + i * 256;
            int kb = idx >> 5, t4 = idx & 31;
            float h0, l0, h1, l1, h2, l2, h3, l3;
            split_tf32(areg[i].x, h0, l0); split_tf32(areg[i].y, h1, l1);
            split_tf32(areg[i].z, h2, l2); split_tf32(areg[i].w, h3, l3);
            *(float4*)&As_hi[kb * BS_STRIDE + t4 * 4] = make_float4(h0, h1, h2, h3);
            *(float4*)&As_lo[kb * BS_STRIDE + t4 * 4] = make_float4(l0, l1, l2, l3);
            split_tf32(breg[i].x, h0, l0); split_tf32(breg[i].y, h1, l1);
            split_tf32(breg[i].z, h2, l2); split_tf32(breg[i].w, h3, l3);
            *(float4*)&Bs_hi[kb * BS_STRIDE + t4 * 4] = make_float4(h0, h1, h2, h3);
            *(float4*)&Bs_lo[kb * BS_STRIDE + t4 * 4] = make_float4(l0, l1, l2, l3);
        }
        __syncthreads();

        if (kt < 31) {
            int kofs = (kt + 1) * 32;
            #pragma unroll
            for (int i = 0; i < 4; i++) {
                int idx = tid + i * 256;
                int kb = idx >> 5, t4 = idx & 31;
                areg[i] = *(const float4*)&g_ctx[(((size_t)(b0 << 10) + kofs + kb) << 10) + t0 + t4 * 4];
                breg[i] = *(const float4*)&W[(kofs + kb) * 1024 + n0 + t4 * 4];
            }
        }

        #pragma unroll
        for (int ks = 0; ks < 4; ks++) {
            const int kk = ks * 8;
            unsigned ah[4][4], al[4][4], bh[4][2], bl[4][2];
            #pragma unroll
            for (int mi = 0; mi < 4; mi++) {
                int mr = wm * 64 + mi * 16 + gid;
                ah[mi][0] = __float_as_uint(As_hi[(kk + tig) * BS_STRIDE + mr]);
                ah[mi][1] = __float_as_uint(As_hi[(kk + tig) * BS_STRIDE + mr + 8]);
                ah[mi][2] = __float_as_uint(As_hi[(kk + tig + 4) * BS_STRIDE + mr]);
                ah[mi][3] = __float_as_uint(As_hi[(kk + tig + 4) * BS_STRIDE + mr + 8]);
                al[mi][0] = __float_as_uint(As_lo[(kk + tig) * BS_STRIDE + mr]);
                al[mi][1] = __float_as_uint(As_lo[(kk + tig) * BS_STRIDE + mr + 8]);
                al[mi][2] = __float_as_uint(As_lo[(kk + tig + 4) * BS_STRIDE + mr]);
                al[mi][3] = __float_as_uint(As_lo[(kk + tig + 4) * BS_STRIDE + mr + 8]);
            }
            #pragma unroll
            for (int ni = 0; ni < 4; ni++) {
                int nc = wn * 32 + ni * 8 + gid;
                bh[ni][0] = __float_as_uint(Bs_hi[(kk + tig) * BS_STRIDE + nc]);
                bh[ni][1] = __float_as_uint(Bs_hi[(kk + tig + 4) * BS_STRIDE + nc]);
                bl[ni][0] = __float_as_uint(Bs_lo[(kk + tig) * BS_STRIDE + nc]);
                bl[ni][1] = __float_as_uint(Bs_lo[(kk + tig + 4) * BS_STRIDE + nc]);
            }
            #pragma unroll
            for (int mi = 0; mi < 4; mi++)
                #pragma unroll
                for (int ni = 0; ni < 4; ni++) {
                    mma_tf32(c[mi][ni], ah[mi], bh[ni]);
                    mma_tf32(c[mi][ni], ah[mi], bl[ni]);
                    mma_tf32(c[mi][ni], al[mi], bh[ni]);
                }
        }
        __syncthreads();
    }

    #pragma unroll
    for (int mi = 0; mi < 4; mi++) {
        #pragma unroll
        for (int r = 0; r < 2; r++) {
            int m = m0 + wm * 64 + mi * 16 + gid + r * 8;
            #pragma unroll
            for (int ni = 0; ni < 4; ni++) {
                int nb = n0 + wn * 32 + ni * 8 + 2 * tig;
                float2 v;
                v.x = c[mi][ni][r * 2 + 0] + bias[nb];
                v.y = c[mi][ni][r * 2 + 1] + bias[nb + 1];
                *(float2*)&g_hidden[(size_t)m * 1024 + nb] = v;
            }
        }
    }
}

// ---------------- FFT + cross spectrum per (b,h,e) row ----------------------
__global__ void __launch_bounds__(256) fft_corr_kernel()
{
    __shared__ float2 Z[1024];
    __shared__ float2 Wt[512];
    const int row = blockIdx.x;
    const int tid = threadIdx.x;
    const float* qr = g_q + (size_t)row * 1024;
    const float* kr = g_k + (size_t)row * 1024;

    for (int j = tid; j < 512; j += 256) {
        float s, c;
        sincospif(-(float)j / 512.0f, &s, &c);
        Wt[j] = make_float2(c, s);
    }
    for (int t = tid; t < 1024; t += 256) {
        int r = __brev((unsigned)t) >> 22;
        Z[r] = make_float2(qr[t], kr[t]);
    }
    __syncthreads();

    #pragma unroll
    for (int s = 0; s < 10; s++) {
        const int half = 1 << s;
        for (int i = tid; i < 512; i += 256) {
            int j = i & (half - 1);
            int p1 = ((i >> s) << (s + 1)) + j;
            int p2 = p1 + half;
            float2 w = Wt[j << (9 - s)];
            float2 z2 = Z[p2], z1 = Z[p1];
            float tr = z2.x * w.x - z2.y * w.y;
            float ti = z2.x * w.y + z2.y * w.x;
            Z[p2] = make_float2(z1.x - tr, z1.y - ti);
            Z[p1] = make_float2(z1.x + tr, z1.y + ti);
        }
        __syncthreads();
    }

    for (int f = F0 + tid; f <= 512; f += 256) {
        float2 A  = Z[f];
        float2 Zc = Z[1024 - f];
        float Br =  Zc.x, Bi = -Zc.y;
        float Ur = A.x + Br, Ui = A.y + Bi;
        float Vr = A.x - Br, Vi = A.y - Bi;
        float Pr = 0.25f * (Ur * Vi - Ui * Vr);
        float Pi = 0.25f * (Ur * Vr + Ui * Vi);
        g_P[(size_t)row * NF + (f - F0)] = make_float2(Pr, Pi);
    }
}

// ---------------- deterministic channel reduction ---------------------------
__global__ void __launch_bounds__(256) reduce_S_kernel()
{
    const int b = blockIdx.x, j = blockIdx.y;
    const int tid = threadIdx.x;
    float2 acc = make_float2(0.f, 0.f);
    for (int r = tid; r < 1024; r += 256) {
        float2 p = g_P[(size_t)((b << 10) + r) * NF + j];
        acc.x += p.x; acc.y += p.y;
    }
    __shared__ float2 sh[256];
    sh[tid] = acc;
    __syncthreads();
    for (int o = 128; o > 0; o >>= 1) {
        if (tid < o) { sh[tid].x += sh[tid + o].x; sh[tid].y += sh[tid + o].y; }
        __syncthreads();
    }
    if (tid == 0) g_S[b][j] = sh[0];
}

// ---------------- irfft of masked spectrum -> mean_value --------------------
__global__ void __launch_bounds__(256) irfft_mean_kernel()
{
    __shared__ float2 tw[1024];
    __shared__ float2 Sb[NF];
    const int b = blockIdx.x;
    const int tid = threadIdx.x;
    for (int j = tid; j < 1024; j += 256) {
        float s, c;
        sincospif((float)j / 512.0f, &s, &c);
        tw[j] = make_float2(c, s);
    }
    for (int j = tid; j < NF; j += 256) Sb[j] = g_S[b][j];
    __syncthreads();

    const int tau = blockIdx.y * 256 + tid;
    float acc = 0.f;
    #pragma unroll 4
    for (int j = 0; j < NF - 1; j++) {
        int id = ((F0 + j) * tau) & 1023;
        float2 s = Sb[j], w = tw[id];
        acc += s.x * w.x - s.y * w.y;
    }
    acc *= 2.0f;
    {
        int id = (512 * tau) & 1023;
        float2 s = Sb[NF - 1], w = tw[id];
        acc += s.x * w.x - s.y * w.y;
    }
    g_mv[b][tau] = acc * (1.0f / (1024.0f * 1024.0f));
}

// ---------------- global top-6 lags + per-batch softmax ---------------------
__global__ void __launch_bounds__(256) topk_kernel()
{
    __shared__ float g[1024];
    __shared__ float rv[256];
    __shared__ int   ri[256];
    __shared__ int   chosen[TOPK];
    const int tid = threadIdx.x;

    for (int t = tid; t < 1024; t += 256) {
        float s = 0.f;
        #pragma unroll
        for (int b = 0; b < BB; b++) s += g_mv[b][t];
        g[t] = s;
    }
    __syncthreads();

    for (int p = 0; p < TOPK; p++) {
        float best = -3.0e38f; int bi = 1 << 30;
        for (int t = tid; t < 1024; t += 256) {
            float v = g[t];
            if (v > best) { best = v; bi = t; }
        }
        rv[tid] = best; ri[tid] = bi;
        __syncthreads();
        for (int o = 128; o > 0; o >>= 1) {
            if (tid < o) {
                float v2 = rv[tid + o]; int i2 = ri[tid + o];
                if (v2 > rv[tid] || (v2 == rv[tid] && i2 < ri[tid])) {
                    rv[tid] = v2; ri[tid] = i2;
                }
            }
            __syncthreads();
        }
        if (tid == 0) { chosen[p] = ri[0]; g[ri[0]] = -3.0e38f; }
        __syncthreads();
    }

    if (tid < BB) {
        int b = tid;
        float w[TOPK], mx = -3.0e38f;
        #pragma unroll
        for (int i = 0; i < TOPK; i++) { w[i] = g_mv[b][chosen[i]]; mx = fmaxf(mx, w[i]); }
        float sum = 0.f;
        #pragma unroll
        for (int i = 0; i < TOPK; i++) { w[i] = expf(w[i] - mx); sum += w[i]; }
        #pragma unroll
        for (int i = 0; i < TOPK; i++) g_tc[b][i] = w[i] / sum;
    }
    if (tid >= 32 && tid < 32 + TOPK) g_idx[tid - 32] = chosen[tid - 32];
}

// ---------------- weighted circular-shift aggregation of v ------------------
__global__ void __launch_bounds__(256) gather_kernel()
{
    __shared__ float vs[1024];
    __shared__ int   sh[TOPK];
    __shared__ float w[TOPK];
    const int row = blockIdx.x;
    const int b = row >> 10;
    const int tid = threadIdx.x;
    for (int t = tid; t < 1024; t += 256) vs[t] = g_v[(size_t)row * 1024 + t];
    if (tid < TOPK) { sh[tid] = g_idx[tid]; w[tid] = g_tc[b][tid]; }
    __syncthreads();
    for (int t = tid; t < 1024; t += 256) {
        float a = 0.f;
        #pragma unroll
        for (int i = 0; i < TOPK; i++) a += w[i] * vs[(t + sh[i]) & 1023];
        g_ctx[(size_t)row * 1024 + t] = a;
    }
}

// ---------------- residual + LayerNorm --------------------------------------
__global__ void __launch_bounds__(256) ln_kernel(
    const float* __restrict__ x, const float* __restrict__ gamma,
    const float* __restrict__ beta, float* __restrict__ out)
{
    const int m = blockIdx.x;
    const int tid = threadIdx.x;
    const float* h  = g_hidden + (size_t)m * 1024;
    const float* xi = x        + (size_t)m * 1024;

    float v[4];
    float s1 = 0.f, s2 = 0.f;
    #pragma unroll
    for (int i = 0; i < 4; i++) {
        float t = h[tid + 256 * i] + xi[tid + 256 * i];
        v[i] = t; s1 += t; s2 += t * t;
    }
    #pragma unroll
    for (int o = 16; o > 0; o >>= 1) {
        s1 += __shfl_xor_sync(0xffffffffu, s1, o);
        s2 += __shfl_xor_sync(0xffffffffu, s2, o);
    }
    __shared__ float w1[8], w2[8];
    __shared__ float sh_mean, sh_inv;
    const int wid = tid >> 5, lane = tid & 31;
    if (lane == 0) { w1[wid] = s1; w2[wid] = s2; }
    __syncthreads();
    if (tid == 0) {
        float a = 0.f, bq = 0.f;
        #pragma unroll
        for (int i = 0; i < 8; i++) { a += w1[i]; bq += w2[i]; }
        float mean = a * (1.0f / 1024.0f);
        float var  = bq * (1.0f / 1024.0f) - mean * mean;
        sh_mean = mean;
        sh_inv  = rsqrtf(var + 1e-12f);
    }
    __syncthreads();
    const float mean = sh_mean, inv = sh_inv;
    #pragma unroll
    for (int i = 0; i < 4; i++) {
        int c = tid + 256 * i;
        out[(size_t)m * 1024 + c] = (v[i] - mean) * inv * gamma[c] + beta[c];
    }
}

// ---------------- launch ----------------------------------------------------
extern "C" void kernel_launch(void* const* d_in, const int* in_sizes, int n_in,
                              void* d_out, int out_size)
{
    (void)in_sizes; (void)n_in; (void)out_size;
    const float* x     = (const float*)d_in[0];
    const float* Wq    = (const float*)d_in[2];
    const float* bq    = (const float*)d_in[3];
    const float* Wk    = (const float*)d_in[4];
    const float* bk    = (const float*)d_in[5];
    const float* Wv    = (const float*)d_in[6];
    const float* bv    = (const float*)d_in[7];
    const float* Wd    = (const float*)d_in[8];
    const float* bd    = (const float*)d_in[9];
    const float* gamma = (const float*)d_in[10];
    const float* beta  = (const float*)d_in[11];
    float* out = (float*)d_out;

    static bool attr_done = false;
    if (!attr_done) {
        cudaFuncSetAttribute(gemm_qkv_mma, cudaFuncAttributeMaxDynamicSharedMemorySize, G1_SMEM);
        cudaFuncSetAttribute(gemm_d_mma,   cudaFuncAttributeMaxDynamicSharedMemorySize, G2_SMEM);
        attr_done = true;
    }

    dim3 ggrid(8, 128);   // N/128 x M/128
    gemm_qkv_mma<<<ggrid, 256, G1_SMEM>>>(x, Wq, bq, 0);
    gemm_qkv_mma<<<ggrid, 256, G1_SMEM>>>(x, Wk, bk, 1);
    gemm_qkv_mma<<<ggrid, 256, G1_SMEM>>>(x, Wv, bv, 2);
    fft_corr_kernel<<<NROW, 256>>>();
    reduce_S_kernel<<<dim3(BB, NF), 256>>>();
    irfft_mean_kernel<<<dim3(BB, 4), 256>>>();
    topk_kernel<<<1, 256>>>();
    gather_kernel<<<NROW, 256>>>();
    gemm_d_mma<<<ggrid, 256, G2_SMEM>>>(Wd, bd);
    ln_kernel<<<NROW, 256>>>(x, gamma, beta, out);
}

// round 6
// speedup vs baseline: 2.2364x; 1.4839x over previous
#include <cuda_runtime.h>
#include <cuda_bf16.h>
#include <cstdint>

// Problem constants
#define BB   16
#define LL   1024
#define HID  1024
#define NROW (BB * HID)
#define NF   308
#define F0   205
#define TOPK 6

// ---------------- scratch (device globals) ----------------------------------
__device__ float  g_q[NROW * LL];        // (B,HID,L)
__device__ float  g_k[NROW * LL];
__device__ float  g_v[NROW * LL];
__device__ float  g_ctxT[NROW * LL];     // (B*L, HID) row-major
__device__ float  g_hidden[NROW * LL];   // (B*L, HID) row-major
__device__ float  g_Wt[4 * HID * HID];   // transposed weights [n][k]; q,k,v,d
__device__ float2 g_P[NROW * NF];
__device__ float2 g_S[BB][NF];
__device__ float  g_mv[BB][LL];
__device__ int    g_idx[TOPK];
__device__ float  g_tc[BB][TOPK];

// ---------------- weight transpose ------------------------------------------
__global__ void __launch_bounds__(256) transpose_w(
    const float* __restrict__ W0, const float* __restrict__ W1,
    const float* __restrict__ W2, const float* __restrict__ W3)
{
    __shared__ float tile[32][33];
    const float* src = (blockIdx.z == 0) ? W0 : (blockIdx.z == 1) ? W1
                     : (blockIdx.z == 2) ? W2 : W3;
    float* dst = g_Wt + (size_t)blockIdx.z * HID * HID;
    const int tx = threadIdx.x & 31, ty = threadIdx.x >> 5;   // 32 x 8
    const int x  = blockIdx.x * 32 + tx;
    const int y0 = blockIdx.y * 32;
    #pragma unroll
    for (int j = 0; j < 32; j += 8)
        tile[ty + j][tx] = src[(size_t)(y0 + ty + j) * HID + x];
    __syncthreads();
    const int x2 = y0 + tx;
    const int y2 = blockIdx.x * 32;
    #pragma unroll
    for (int j = 0; j < 32; j += 8)
        dst[(size_t)(y2 + ty + j) * HID + x2] = tile[tx][ty + j];
}

// ---------------- bf16-split GEMM (mma.m16n8k16) -----------------------------
// smem per buffer: 4 arrays (Ahi, Alo, Bhi, Blo), each 128 rows x 64B,
// 16B chunks XOR-swizzled: chunk' = chunk ^ ((row>>1)&3)
#define ARR_B 8192                    // 128 * 64
#define BUF_B (4 * ARR_B)             // 32768
#define GSMEM (2 * BUF_B)             // 65536

__device__ __forceinline__ void split_pack(float4 v, uint2& hi, uint2& lo) {
    __nv_bfloat162 h01 = __floats2bfloat162_rn(v.x, v.y);
    __nv_bfloat162 h23 = __floats2bfloat162_rn(v.z, v.w);
    float2 f01 = __bfloat1622float2(h01);
    float2 f23 = __bfloat1622float2(h23);
    __nv_bfloat162 l01 = __floats2bfloat162_rn(v.x - f01.x, v.y - f01.y);
    __nv_bfloat162 l23 = __floats2bfloat162_rn(v.z - f23.x, v.w - f23.y);
    hi.x = *(unsigned*)&h01; hi.y = *(unsigned*)&h23;
    lo.x = *(unsigned*)&l01; lo.y = *(unsigned*)&l23;
}
__device__ __forceinline__ void mma_bf16(float* c, const unsigned* a, const unsigned* b) {
    asm volatile(
        "mma.sync.aligned.m16n8k16.row.col.f32.bf16.bf16.f32 "
        "{%0,%1,%2,%3}, {%4,%5,%6,%7}, {%8,%9}, {%0,%1,%2,%3};"
        : "+f"(c[0]), "+f"(c[1]), "+f"(c[2]), "+f"(c[3])
        : "r"(a[0]), "r"(a[1]), "r"(a[2]), "r"(a[3]), "r"(b[0]), "r"(b[1]));
}
__device__ __forceinline__ void ldsm4(unsigned* r, uint32_t addr) {
    asm volatile("ldmatrix.sync.aligned.m8n8.x4.shared.b16 {%0,%1,%2,%3}, [%4];"
        : "=r"(r[0]), "=r"(r[1]), "=r"(r[2]), "=r"(r[3]) : "r"(addr));
}
__device__ __forceinline__ void ldsm2(unsigned* r, uint32_t addr) {
    asm volatile("ldmatrix.sync.aligned.m8n8.x2.shared.b16 {%0,%1}, [%2];"
        : "=r"(r[0]), "=r"(r[1]) : "r"(addr));
}

__global__ void __launch_bounds__(256) gemm_bf16(
    const float* __restrict__ Ain, const float* __restrict__ bias, int which)
{
    extern __shared__ char smem[];
    const uint32_t sbase = (uint32_t)__cvta_generic_to_shared(smem);

    const float* A  = (which == 3) ? g_ctxT : Ain;
    const float* Bt = g_Wt + (size_t)which * HID * HID;
    float* Out = (which == 0) ? g_q : (which == 1) ? g_k
               : (which == 2) ? g_v : g_hidden;

    const int m0 = blockIdx.y * 128;
    const int n0 = blockIdx.x * 128;
    const int tid  = threadIdx.x;
    const int lane = tid & 31;
    const int wid  = tid >> 5;
    const int wm = wid & 1;
    const int wn = wid >> 1;
    const int gid = lane >> 2;
    const int tig = lane & 3;

    // store offsets (constant per thread): idx = tid + i*256
    uint32_t st_off[4];
    #pragma unroll
    for (int i = 0; i < 4; i++) {
        int idx = tid + i * 256;
        int row = idx >> 3, kq = idx & 7;       // kq: 8B units within 64B row
        st_off[i] = (uint32_t)row * 64 + (uint32_t)(((kq >> 1) ^ ((row >> 1) & 3)) << 4)
                  + (uint32_t)((kq & 1) << 3);
    }

    // ldmatrix per-lane bases
    const int a_rowb = wm * 64 + ((lane >> 3) & 1) * 8 + (lane & 7);  // + mi*16
    const int a_cbit = (lane >> 4) & 1;
    const int b_rowb = wn * 32 + (lane & 7);                          // + ni*8
    const int b_cbit = (lane >> 3) & 1;

    uint32_t a_rb[4], b_rb[4];
    int a_swz[4], b_swz[4];
    #pragma unroll
    for (int mi = 0; mi < 4; mi++) {
        int r = a_rowb + mi * 16;
        a_rb[mi] = (uint32_t)r * 64;
        a_swz[mi] = (r >> 1) & 3;
    }
    #pragma unroll
    for (int ni = 0; ni < 4; ni++) {
        int r = b_rowb + ni * 8;
        b_rb[ni] = (uint32_t)r * 64;
        b_swz[ni] = (r >> 1) & 3;
    }

    float c[4][4][4];
    #pragma unroll
    for (int i = 0; i < 4; i++)
        #pragma unroll
        for (int j = 0; j < 4; j++)
            #pragma unroll
            for (int r = 0; r < 4; r++) c[i][j][r] = 0.f;

    float4 areg[4], breg[4];
    #pragma unroll
    for (int i = 0; i < 4; i++) {
        int idx = tid + i * 256;
        areg[i] = *(const float4*)&A [(size_t)(m0 + (idx >> 3)) * 1024 + (idx & 7) * 4];
        breg[i] = *(const float4*)&Bt[(size_t)(n0 + (idx >> 3)) * 1024 + (idx & 7) * 4];
    }
    // split + store tile 0 into buffer 0
    {
        char* sp = smem;
        #pragma unroll
        for (int i = 0; i < 4; i++) {
            uint2 hi, lo;
            split_pack(areg[i], hi, lo);
            *(uint2*)(sp + st_off[i])             = hi;
            *(uint2*)(sp + ARR_B + st_off[i])     = lo;
            split_pack(breg[i], hi, lo);
            *(uint2*)(sp + 2 * ARR_B + st_off[i]) = hi;
            *(uint2*)(sp + 3 * ARR_B + st_off[i]) = lo;
        }
    }
    __syncthreads();

    for (int kt = 0; kt < 32; kt++) {
        if (kt < 31) {
            int k0 = (kt + 1) * 32;
            #pragma unroll
            for (int i = 0; i < 4; i++) {
                int idx = tid + i * 256;
                areg[i] = *(const float4*)&A [(size_t)(m0 + (idx >> 3)) * 1024 + k0 + (idx & 7) * 4];
                breg[i] = *(const float4*)&Bt[(size_t)(n0 + (idx >> 3)) * 1024 + k0 + (idx & 7) * 4];
            }
        }

        const uint32_t sb = sbase + (uint32_t)(kt & 1) * BUF_B;
        #pragma unroll
        for (int ks = 0; ks < 2; ks++) {
            unsigned ah[4][4], al[4][4], bh[4][2], bl[4][2];
            const int cbase = ks * 2;
            #pragma unroll
            for (int mi = 0; mi < 4; mi++) {
                uint32_t ad = sb + a_rb[mi]
                            + (uint32_t)((((cbase | a_cbit) ^ a_swz[mi]) << 4));
                ldsm4(ah[mi], ad);
                ldsm4(al[mi], ad + ARR_B);
            }
            #pragma unroll
            for (int ni = 0; ni < 4; ni++) {
                uint32_t bd = sb + 2 * ARR_B + b_rb[ni]
                            + (uint32_t)((((cbase | b_cbit) ^ b_swz[ni]) << 4));
                ldsm2(bh[ni], bd);
                ldsm2(bl[ni], bd + ARR_B);
            }
            #pragma unroll
            for (int mi = 0; mi < 4; mi++)
                #pragma unroll
                for (int ni = 0; ni < 4; ni++) {
                    mma_bf16(c[mi][ni], ah[mi], bh[ni]);
                    mma_bf16(c[mi][ni], ah[mi], bl[ni]);
                    mma_bf16(c[mi][ni], al[mi], bh[ni]);
                }
        }

        if (kt < 31) {
            char* sp = smem + ((kt + 1) & 1) * BUF_B;
            #pragma unroll
            for (int i = 0; i < 4; i++) {
                uint2 hi, lo;
                split_pack(areg[i], hi, lo);
                *(uint2*)(sp + st_off[i])             = hi;
                *(uint2*)(sp + ARR_B + st_off[i])     = lo;
                split_pack(breg[i], hi, lo);
                *(uint2*)(sp + 2 * ARR_B + st_off[i]) = hi;
                *(uint2*)(sp + 3 * ARR_B + st_off[i]) = lo;
            }
            __syncthreads();
        }
    }

    // epilogue
    if (which < 3) {
        const int bidx = m0 >> 10;
        #pragma unroll
        for (int mi = 0; mi < 4; mi++) {
            #pragma unroll
            for (int r = 0; r < 2; r++) {
                int m = m0 + wm * 64 + mi * 16 + gid + r * 8;
                int t = m & 1023;
                #pragma unroll
                for (int ni = 0; ni < 4; ni++) {
                    int nb = n0 + wn * 32 + ni * 8 + 2 * tig;
                    float v0 = c[mi][ni][r * 2 + 0] + bias[nb];
                    float v1 = c[mi][ni][r * 2 + 1] + bias[nb + 1];
                    Out[(((size_t)(bidx << 10) + nb) << 10) + t] = v0;
                    Out[(((size_t)(bidx << 10) + nb + 1) << 10) + t] = v1;
                }
            }
        }
    } else {
        #pragma unroll
        for (int mi = 0; mi < 4; mi++) {
            #pragma unroll
            for (int r = 0; r < 2; r++) {
                int m = m0 + wm * 64 + mi * 16 + gid + r * 8;
                #pragma unroll
                for (int ni = 0; ni < 4; ni++) {
                    int nb = n0 + wn * 32 + ni * 8 + 2 * tig;
                    float2 v;
                    v.x = c[mi][ni][r * 2 + 0] + bias[nb];
                    v.y = c[mi][ni][r * 2 + 1] + bias[nb + 1];
                    *(float2*)&Out[(size_t)m * 1024 + nb] = v;
                }
            }
        }
    }
}

// ---------------- FFT + cross spectrum per (b,h,e) row ----------------------
__global__ void __launch_bounds__(256) fft_corr_kernel()
{
    __shared__ float2 Z[1024];
    __shared__ float2 Wt[512];
    const int row = blockIdx.x;
    const int tid = threadIdx.x;
    const float* qr = g_q + (size_t)row * 1024;
    const float* kr = g_k + (size_t)row * 1024;

    for (int j = tid; j < 512; j += 256) {
        float s, c;
        sincospif(-(float)j / 512.0f, &s, &c);
        Wt[j] = make_float2(c, s);
    }
    for (int t = tid; t < 1024; t += 256) {
        int r = __brev((unsigned)t) >> 22;
        Z[r] = make_float2(qr[t], kr[t]);
    }
    __syncthreads();

    #pragma unroll
    for (int s = 0; s < 10; s++) {
        const int half = 1 << s;
        for (int i = tid; i < 512; i += 256) {
            int j = i & (half - 1);
            int p1 = ((i >> s) << (s + 1)) + j;
            int p2 = p1 + half;
            float2 w = Wt[j << (9 - s)];
            float2 z2 = Z[p2], z1 = Z[p1];
            float tr = z2.x * w.x - z2.y * w.y;
            float ti = z2.x * w.y + z2.y * w.x;
            Z[p2] = make_float2(z1.x - tr, z1.y - ti);
            Z[p1] = make_float2(z1.x + tr, z1.y + ti);
        }
        __syncthreads();
    }

    for (int f = F0 + tid; f <= 512; f += 256) {
        float2 A  = Z[f];
        float2 Zc = Z[1024 - f];
        float Br =  Zc.x, Bi = -Zc.y;
        float Ur = A.x + Br, Ui = A.y + Bi;
        float Vr = A.x - Br, Vi = A.y - Bi;
        float Pr = 0.25f * (Ur * Vi - Ui * Vr);
        float Pi = 0.25f * (Ur * Vr + Ui * Vi);
        g_P[(size_t)row * NF + (f - F0)] = make_float2(Pr, Pi);
    }
}

// ---------------- deterministic channel reduction ---------------------------
__global__ void __launch_bounds__(256) reduce_S_kernel()
{
    const int b = blockIdx.x, j = blockIdx.y;
    const int tid = threadIdx.x;
    float2 acc = make_float2(0.f, 0.f);
    for (int r = tid; r < 1024; r += 256) {
        float2 p = g_P[(size_t)((b << 10) + r) * NF + j];
        acc.x += p.x; acc.y += p.y;
    }
    __shared__ float2 sh[256];
    sh[tid] = acc;
    __syncthreads();
    for (int o = 128; o > 0; o >>= 1) {
        if (tid < o) { sh[tid].x += sh[tid + o].x; sh[tid].y += sh[tid + o].y; }
        __syncthreads();
    }
    if (tid == 0) g_S[b][j] = sh[0];
}

// ---------------- irfft of masked spectrum -> mean_value --------------------
__global__ void __launch_bounds__(256) irfft_mean_kernel()
{
    __shared__ float2 tw[1024];
    __shared__ float2 Sb[NF];
    const int b = blockIdx.x;
    const int tid = threadIdx.x;
    for (int j = tid; j < 1024; j += 256) {
        float s, c;
        sincospif((float)j / 512.0f, &s, &c);
        tw[j] = make_float2(c, s);
    }
    for (int j = tid; j < NF; j += 256) Sb[j] = g_S[b][j];
    __syncthreads();

    const int tau = blockIdx.y * 256 + tid;
    float acc = 0.f;
    #pragma unroll 4
    for (int j = 0; j < NF - 1; j++) {
        int id = ((F0 + j) * tau) & 1023;
        float2 s = Sb[j], w = tw[id];
        acc += s.x * w.x - s.y * w.y;
    }
    acc *= 2.0f;
    {
        int id = (512 * tau) & 1023;
        float2 s = Sb[NF - 1], w = tw[id];
        acc += s.x * w.x - s.y * w.y;
    }
    g_mv[b][tau] = acc * (1.0f / (1024.0f * 1024.0f));
}

// ---------------- global top-6 lags + per-batch softmax ---------------------
__global__ void __launch_bounds__(256) topk_kernel()
{
    __shared__ float g[1024];
    __shared__ float rv[256];
    __shared__ int   ri[256];
    __shared__ int   chosen[TOPK];
    const int tid = threadIdx.x;

    for (int t = tid; t < 1024; t += 256) {
        float s = 0.f;
        #pragma unroll
        for (int b = 0; b < BB; b++) s += g_mv[b][t];
        g[t] = s;
    }
    __syncthreads();

    for (int p = 0; p < TOPK; p++) {
        float best = -3.0e38f; int bi = 1 << 30;
        for (int t = tid; t < 1024; t += 256) {
            float v = g[t];
            if (v > best) { best = v; bi = t; }
        }
        rv[tid] = best; ri[tid] = bi;
        __syncthreads();
        for (int o = 128; o > 0; o >>= 1) {
            if (tid < o) {
                float v2 = rv[tid + o]; int i2 = ri[tid + o];
                if (v2 > rv[tid] || (v2 == rv[tid] && i2 < ri[tid])) {
                    rv[tid] = v2; ri[tid] = i2;
                }
            }
            __syncthreads();
        }
        if (tid == 0) { chosen[p] = ri[0]; g[ri[0]] = -3.0e38f; }
        __syncthreads();
    }

    if (tid < BB) {
        int b = tid;
        float w[TOPK], mx = -3.0e38f;
        #pragma unroll
        for (int i = 0; i < TOPK; i++) { w[i] = g_mv[b][chosen[i]]; mx = fmaxf(mx, w[i]); }
        float sum = 0.f;
        #pragma unroll
        for (int i = 0; i < TOPK; i++) { w[i] = expf(w[i] - mx); sum += w[i]; }
        #pragma unroll
        for (int i = 0; i < TOPK; i++) g_tc[b][i] = w[i] / sum;
    }
    if (tid >= 32 && tid < 32 + TOPK) g_idx[tid - 32] = chosen[tid - 32];
}

// ---------------- fused weighted shift-aggregation + transpose --------------
// block: (b, c-tile of 32); out ctxT[(b*L + t)*HID + c]
#define GT_SMEM (32 * 1025 * 4)
__global__ void __launch_bounds__(256) gatherT_kernel()
{
    extern __shared__ float vs[];            // [32][1025]
    __shared__ int   sh[TOPK];
    __shared__ float w[TOPK];
    const int b  = blockIdx.y;
    const int c0 = blockIdx.x * 32;
    const int tid = threadIdx.x;
    if (tid < TOPK) { sh[tid] = g_idx[tid]; w[tid] = g_tc[b][tid]; }
    for (int idx = tid; idx < 32 * 1024; idx += 256) {
        int r = idx >> 10, t = idx & 1023;
        vs[r * 1025 + t] = g_v[((size_t)(b << 10) + c0 + r) * 1024 + t];
    }
    __syncthreads();
    const int cc = tid & 31;
    for (int tt = tid >> 5; tt < 1024; tt += 8) {
        float a = 0.f;
        #pragma unroll
        for (int i = 0; i < TOPK; i++)
            a += w[i] * vs[cc * 1025 + ((tt + sh[i]) & 1023)];
        g_ctxT[((size_t)(b << 10) + tt) * 1024 + c0 + cc] = a;
    }
}

// ---------------- residual + LayerNorm --------------------------------------
__global__ void __launch_bounds__(256) ln_kernel(
    const float* __restrict__ x, const float* __restrict__ gamma,
    const float* __restrict__ beta, float* __restrict__ out)
{
    const int m = blockIdx.x;
    const int tid = threadIdx.x;
    const float* h  = g_hidden + (size_t)m * 1024;
    const float* xi = x        + (size_t)m * 1024;

    float v[4];
    float s1 = 0.f, s2 = 0.f;
    #pragma unroll
    for (int i = 0; i < 4; i++) {
        float t = h[tid + 256 * i] + xi[tid + 256 * i];
        v[i] = t; s1 += t; s2 += t * t;
    }
    #pragma unroll
    for (int o = 16; o > 0; o >>= 1) {
        s1 += __shfl_xor_sync(0xffffffffu, s1, o);
        s2 += __shfl_xor_sync(0xffffffffu, s2, o);
    }
    __shared__ float w1[8], w2[8];
    __shared__ float sh_mean, sh_inv;
    const int wid = tid >> 5, lane = tid & 31;
    if (lane == 0) { w1[wid] = s1; w2[wid] = s2; }
    __syncthreads();
    if (tid == 0) {
        float a = 0.f, bq = 0.f;
        #pragma unroll
        for (int i = 0; i < 8; i++) { a += w1[i]; bq += w2[i]; }
        float mean = a * (1.0f / 1024.0f);
        float var  = bq * (1.0f / 1024.0f) - mean * mean;
        sh_mean = mean;
        sh_inv  = rsqrtf(var + 1e-12f);
    }
    __syncthreads();
    const float mean = sh_mean, inv = sh_inv;
    #pragma unroll
    for (int i = 0; i < 4; i++) {
        int c = tid + 256 * i;
        out[(size_t)m * 1024 + c] = (v[i] - mean) * inv * gamma[c] + beta[c];
    }
}

// ---------------- launch ----------------------------------------------------
extern "C" void kernel_launch(void* const* d_in, const int* in_sizes, int n_in,
                              void* d_out, int out_size)
{
    (void)in_sizes; (void)n_in; (void)out_size;
    const float* x     = (const float*)d_in[0];
    const float* Wq    = (const float*)d_in[2];
    const float* bq    = (const float*)d_in[3];
    const float* Wk    = (const float*)d_in[4];
    const float* bk    = (const float*)d_in[5];
    const float* Wv    = (const float*)d_in[6];
    const float* bv    = (const float*)d_in[7];
    const float* Wd    = (const float*)d_in[8];
    const float* bd    = (const float*)d_in[9];
    const float* gamma = (const float*)d_in[10];
    const float* beta  = (const float*)d_in[11];
    float* out = (float*)d_out;

    static bool attr_done = false;
    if (!attr_done) {
        cudaFuncSetAttribute(gemm_bf16,      cudaFuncAttributeMaxDynamicSharedMemorySize, GSMEM);
        cudaFuncSetAttribute(gatherT_kernel, cudaFuncAttributeMaxDynamicSharedMemorySize, GT_SMEM);
        attr_done = true;
    }

    dim3 ggrid(8, 128);   // N/128 x M/128
    transpose_w<<<dim3(32, 32, 4), 256>>>(Wq, Wk, Wv, Wd);
    gemm_bf16<<<ggrid, 256, GSMEM>>>(x, bq, 0);
    gemm_bf16<<<ggrid, 256, GSMEM>>>(x, bk, 1);
    gemm_bf16<<<ggrid, 256, GSMEM>>>(x, bv, 2);
    fft_corr_kernel<<<NROW, 256>>>();
    reduce_S_kernel<<<dim3(BB, NF), 256>>>();
    irfft_mean_kernel<<<dim3(BB, 4), 256>>>();
    topk_kernel<<<1, 256>>>();
    gatherT_kernel<<<dim3(32, BB), 256, GT_SMEM>>>();
    gemm_bf16<<<ggrid, 256, GSMEM>>>(nullptr, bd, 3);
    ln_kernel<<<NROW, 256>>>(x, gamma, beta, out);
}

// round 7
// speedup vs baseline: 2.5654x; 1.1471x over previous
#include <cuda_runtime.h>
#include <cuda_bf16.h>
#include <cstdint>

// Problem constants
#define BB   16
#define LL   1024
#define HID  1024
#define NROW (BB * HID)
#define NF   308
#define F0   205
#define TOPK 6

// ---------------- scratch (device globals) ----------------------------------
__device__ float  g_q[NROW * LL];        // (B,HID,L)
__device__ float  g_k[NROW * LL];
__device__ float  g_v[NROW * LL];
__device__ float  g_hidden[NROW * LL];   // (B*L, HID) row-major
__device__ __nv_bfloat16 g_x_hi[NROW * LL];    // x split, (B*L, HID)
__device__ __nv_bfloat16 g_x_lo[NROW * LL];
__device__ __nv_bfloat16 g_wt_hi[4 * HID * HID];  // transposed weights [n][k]
__device__ __nv_bfloat16 g_wt_lo[4 * HID * HID];
__device__ __nv_bfloat16 g_ctx_hi[NROW * LL];     // ctx (B*L, HID)
__device__ __nv_bfloat16 g_ctx_lo[NROW * LL];
__device__ float2 g_P[NROW * NF];
__device__ float2 g_S[BB][NF];
__device__ float  g_mv[BB][LL];
__device__ int    g_idx[TOPK];
__device__ float  g_tc[BB][TOPK];

// ---------------- split helpers ---------------------------------------------
__device__ __forceinline__ void split1(float x, __nv_bfloat16& h, __nv_bfloat16& l) {
    h = __float2bfloat16(x);
    l = __float2bfloat16(x - __bfloat162float(h));
}

// x -> bf16 hi/lo (done once; feeds all 3 QKV GEMMs)
__global__ void __launch_bounds__(256) split_x_kernel(const float* __restrict__ x)
{
    size_t i = ((size_t)blockIdx.x * 256 + threadIdx.x) * 4;
    float4 v = *(const float4*)&x[i];
    __nv_bfloat16 h0, l0, h1, l1, h2, l2, h3, l3;
    split1(v.x, h0, l0); split1(v.y, h1, l1);
    split1(v.z, h2, l2); split1(v.w, h3, l3);
    __nv_bfloat162 hh01 = {h0, h1}, hh23 = {h2, h3};
    __nv_bfloat162 ll01 = {l0, l1}, ll23 = {l2, l3};
    uint2 hi, lo;
    hi.x = *(unsigned*)&hh01; hi.y = *(unsigned*)&hh23;
    lo.x = *(unsigned*)&ll01; lo.y = *(unsigned*)&ll23;
    *(uint2*)&g_x_hi[i] = hi;
    *(uint2*)&g_x_lo[i] = lo;
}

// ---------------- weight transpose + split ----------------------------------
__global__ void __launch_bounds__(256) transpose_w(
    const float* __restrict__ W0, const float* __restrict__ W1,
    const float* __restrict__ W2, const float* __restrict__ W3)
{
    __shared__ float tile[32][33];
    const float* src = (blockIdx.z == 0) ? W0 : (blockIdx.z == 1) ? W1
                     : (blockIdx.z == 2) ? W2 : W3;
    __nv_bfloat16* dh = g_wt_hi + (size_t)blockIdx.z * HID * HID;
    __nv_bfloat16* dl = g_wt_lo + (size_t)blockIdx.z * HID * HID;
    const int tx = threadIdx.x & 31, ty = threadIdx.x >> 5;   // 32 x 8
    const int x  = blockIdx.x * 32 + tx;
    const int y0 = blockIdx.y * 32;
    #pragma unroll
    for (int j = 0; j < 32; j += 8)
        tile[ty + j][tx] = src[(size_t)(y0 + ty + j) * HID + x];
    __syncthreads();
    const int x2 = y0 + tx;
    const int y2 = blockIdx.x * 32;
    #pragma unroll
    for (int j = 0; j < 32; j += 8) {
        float v = tile[tx][ty + j];
        __nv_bfloat16 h, l;
        split1(v, h, l);
        dh[(size_t)(y2 + ty + j) * HID + x2] = h;
        dl[(size_t)(y2 + ty + j) * HID + x2] = l;
    }
}

// ---------------- bf16-split GEMM, cp.async 4-stage pipeline ----------------
// smem per stage: 4 arrays (Ahi, Alo, Bhi, Blo), each 128 rows x 64B,
// 16B chunks XOR-swizzled: chunk' = chunk ^ ((row>>1)&3)
#define ARRB   8192                   // 128 * 64
#define STAGEB (4 * ARRB)             // 32768
#define GSMEM  (4 * STAGEB)           // 131072

__device__ __forceinline__ void mma_bf16(float* c, const unsigned* a, const unsigned* b) {
    asm volatile(
        "mma.sync.aligned.m16n8k16.row.col.f32.bf16.bf16.f32 "
        "{%0,%1,%2,%3}, {%4,%5,%6,%7}, {%8,%9}, {%0,%1,%2,%3};"
        : "+f"(c[0]), "+f"(c[1]), "+f"(c[2]), "+f"(c[3])
        : "r"(a[0]), "r"(a[1]), "r"(a[2]), "r"(a[3]), "r"(b[0]), "r"(b[1]));
}
__device__ __forceinline__ void ldsm4(unsigned* r, uint32_t addr) {
    asm volatile("ldmatrix.sync.aligned.m8n8.x4.shared.b16 {%0,%1,%2,%3}, [%4];"
        : "=r"(r[0]), "=r"(r[1]), "=r"(r[2]), "=r"(r[3]) : "r"(addr));
}
__device__ __forceinline__ void ldsm2(unsigned* r, uint32_t addr) {
    asm volatile("ldmatrix.sync.aligned.m8n8.x2.shared.b16 {%0,%1}, [%2];"
        : "=r"(r[0]), "=r"(r[1]) : "r"(addr));
}
__device__ __forceinline__ void cpasync16(uint32_t dst, const void* src) {
    asm volatile("cp.async.cg.shared.global [%0], [%1], 16;" :: "r"(dst), "l"(src));
}

__device__ __forceinline__ void issue_stage(
    uint32_t sb,
    const __nv_bfloat16* __restrict__ Ah, const __nv_bfloat16* __restrict__ Al,
    const __nv_bfloat16* __restrict__ Bh, const __nv_bfloat16* __restrict__ Bl,
    int m0, int n0, int k0, int tid)
{
    #pragma unroll
    for (int c = 0; c < 2; c++) {
        int chunk = tid + c * 256;
        int row = chunk >> 2, ch = chunk & 3;
        uint32_t so = (uint32_t)row * 64 + (uint32_t)((ch ^ ((row >> 1) & 3)) << 4);
        size_t ga = (size_t)(m0 + row) * 1024 + k0 + ch * 8;
        size_t gb = (size_t)(n0 + row) * 1024 + k0 + ch * 8;
        cpasync16(sb + so,            Ah + ga);
        cpasync16(sb + ARRB + so,     Al + ga);
        cpasync16(sb + 2 * ARRB + so, Bh + gb);
        cpasync16(sb + 3 * ARRB + so, Bl + gb);
    }
}

__global__ void __launch_bounds__(256) gemm_bf16(
    const float* __restrict__ bias, int which)
{
    extern __shared__ char smem[];
    const uint32_t sbase = (uint32_t)__cvta_generic_to_shared(smem);

    const __nv_bfloat16* Ah = (which == 3) ? g_ctx_hi : g_x_hi;
    const __nv_bfloat16* Al = (which == 3) ? g_ctx_lo : g_x_lo;
    const __nv_bfloat16* Bh = g_wt_hi + (size_t)which * HID * HID;
    const __nv_bfloat16* Bl = g_wt_lo + (size_t)which * HID * HID;
    float* Out = (which == 0) ? g_q : (which == 1) ? g_k
               : (which == 2) ? g_v : g_hidden;

    const int m0 = blockIdx.y * 128;
    const int n0 = blockIdx.x * 128;
    const int tid  = threadIdx.x;
    const int lane = tid & 31;
    const int wid  = tid >> 5;
    const int wm = wid & 1;
    const int wn = wid >> 1;
    const int gid = lane >> 2;
    const int tig = lane & 3;

    // ldmatrix per-lane bases
    const int a_rowb = wm * 64 + ((lane >> 3) & 1) * 8 + (lane & 7);  // + mi*16
    const int a_cbit = (lane >> 4) & 1;
    const int b_rowb = wn * 32 + (lane & 7);                          // + ni*8
    const int b_cbit = (lane >> 3) & 1;

    uint32_t a_rb[4], b_rb[4];
    int a_swz[4], b_swz[4];
    #pragma unroll
    for (int mi = 0; mi < 4; mi++) {
        int r = a_rowb + mi * 16;
        a_rb[mi] = (uint32_t)r * 64;
        a_swz[mi] = (r >> 1) & 3;
    }
    #pragma unroll
    for (int ni = 0; ni < 4; ni++) {
        int r = b_rowb + ni * 8;
        b_rb[ni] = (uint32_t)r * 64;
        b_swz[ni] = (r >> 1) & 3;
    }

    float c[4][4][4];
    #pragma unroll
    for (int i = 0; i < 4; i++)
        #pragma unroll
        for (int j = 0; j < 4; j++)
            #pragma unroll
            for (int r = 0; r < 4; r++) c[i][j][r] = 0.f;

    // prologue: prefetch stages 0..2
    issue_stage(sbase + 0 * STAGEB, Ah, Al, Bh, Bl, m0, n0, 0,  tid);
    asm volatile("cp.async.commit_group;");
    issue_stage(sbase + 1 * STAGEB, Ah, Al, Bh, Bl, m0, n0, 32, tid);
    asm volatile("cp.async.commit_group;");
    issue_stage(sbase + 2 * STAGEB, Ah, Al, Bh, Bl, m0, n0, 64, tid);
    asm volatile("cp.async.commit_group;");

    for (int kt = 0; kt < 32; kt++) {
        asm volatile("cp.async.wait_group 2;");
        __syncthreads();

        if (kt + 3 < 32)
            issue_stage(sbase + ((kt + 3) & 3) * STAGEB, Ah, Al, Bh, Bl,
                        m0, n0, (kt + 3) * 32, tid);
        asm volatile("cp.async.commit_group;");

        const uint32_t sb = sbase + (uint32_t)(kt & 3) * STAGEB;
        #pragma unroll
        for (int ks = 0; ks < 2; ks++) {
            unsigned ah[4][4], al[4][4], bh[4][2], bl[4][2];
            const int cbase = ks * 2;
            #pragma unroll
            for (int mi = 0; mi < 4; mi++) {
                uint32_t ad = sb + a_rb[mi]
                            + (uint32_t)((((cbase | a_cbit) ^ a_swz[mi]) << 4));
                ldsm4(ah[mi], ad);
                ldsm4(al[mi], ad + ARRB);
            }
            #pragma unroll
            for (int ni = 0; ni < 4; ni++) {
                uint32_t bd = sb + 2 * ARRB + b_rb[ni]
                            + (uint32_t)((((cbase | b_cbit) ^ b_swz[ni]) << 4));
                ldsm2(bh[ni], bd);
                ldsm2(bl[ni], bd + ARRB);
            }
            #pragma unroll
            for (int mi = 0; mi < 4; mi++)
                #pragma unroll
                for (int ni = 0; ni < 4; ni++) {
                    mma_bf16(c[mi][ni], ah[mi], bh[ni]);
                    mma_bf16(c[mi][ni], ah[mi], bl[ni]);
                    mma_bf16(c[mi][ni], al[mi], bh[ni]);
                }
        }
    }

    // epilogue
    if (which < 3) {
        const int bidx = m0 >> 10;
        #pragma unroll
        for (int mi = 0; mi < 4; mi++) {
            #pragma unroll
            for (int r = 0; r < 2; r++) {
                int m = m0 + wm * 64 + mi * 16 + gid + r * 8;
                int t = m & 1023;
                #pragma unroll
                for (int ni = 0; ni < 4; ni++) {
                    int nb = n0 + wn * 32 + ni * 8 + 2 * tig;
                    float v0 = c[mi][ni][r * 2 + 0] + bias[nb];
                    float v1 = c[mi][ni][r * 2 + 1] + bias[nb + 1];
                    Out[(((size_t)(bidx << 10) + nb) << 10) + t] = v0;
                    Out[(((size_t)(bidx << 10) + nb + 1) << 10) + t] = v1;
                }
            }
        }
    } else {
        #pragma unroll
        for (int mi = 0; mi < 4; mi++) {
            #pragma unroll
            for (int r = 0; r < 2; r++) {
                int m = m0 + wm * 64 + mi * 16 + gid + r * 8;
                #pragma unroll
                for (int ni = 0; ni < 4; ni++) {
                    int nb = n0 + wn * 32 + ni * 8 + 2 * tig;
                    float2 v;
                    v.x = c[mi][ni][r * 2 + 0] + bias[nb];
                    v.y = c[mi][ni][r * 2 + 1] + bias[nb + 1];
                    *(float2*)&Out[(size_t)m * 1024 + nb] = v;
                }
            }
        }
    }
}

// ---------------- radix-4 DIF FFT + cross spectrum --------------------------
// z = q + i*k; 1024-pt FFT in 5 radix-4 stages, output base-4 digit-reversed.
// Bank swizzle phys = p ^ ((p>>2)&15) -> conflict-free float2 access all stages.
__device__ __forceinline__ int fswz(int p) { return p ^ ((p >> 2) & 15); }
__device__ __forceinline__ int rev4(int x) {
    return ((x & 3) << 8) | (((x >> 2) & 3) << 6) | (((x >> 4) & 3) << 4)
         | (((x >> 6) & 3) << 2) | ((x >> 8) & 3);
}
__device__ __forceinline__ float2 cmul(float2 a, float2 w) {
    return make_float2(a.x * w.x - a.y * w.y, a.x * w.y + a.y * w.x);
}

__global__ void __launch_bounds__(256) fft_corr_kernel()
{
    __shared__ float2 Zs[1024];
    __shared__ float2 tw[1024];
    const int row = blockIdx.x;
    const int t = threadIdx.x;
    const float* qr = g_q + (size_t)row * 1024;
    const float* kr = g_k + (size_t)row * 1024;

    for (int j = t; j < 1024; j += 256) {
        float s, c;
        sincospif(-(float)j / 512.0f, &s, &c);   // e^{-2*pi*i*j/1024}
        tw[j] = make_float2(c, s);
    }
    __syncthreads();

    // stage 0 (quarter=256) directly from global
    {
        float2 x0 = make_float2(qr[t],       kr[t]);
        float2 x1 = make_float2(qr[t + 256], kr[t + 256]);
        float2 x2 = make_float2(qr[t + 512], kr[t + 512]);
        float2 x3 = make_float2(qr[t + 768], kr[t + 768]);
        float2 p02 = make_float2(x0.x + x2.x, x0.y + x2.y);
        float2 m02 = make_float2(x0.x - x2.x, x0.y - x2.y);
        float2 p13 = make_float2(x1.x + x3.x, x1.y + x3.y);
        float2 m13 = make_float2(x1.x - x3.x, x1.y - x3.y);
        float2 y0 = make_float2(p02.x + p13.x, p02.y + p13.y);
        float2 y2 = make_float2(p02.x - p13.x, p02.y - p13.y);
        float2 y1 = make_float2(m02.x + m13.y, m02.y - m13.x);  // m02 - i*m13
        float2 y3 = make_float2(m02.x - m13.y, m02.y + m13.x);  // m02 + i*m13
        int e = t;
        Zs[fswz(t)]       = y0;
        Zs[fswz(t + 256)] = cmul(y1, tw[e]);
        Zs[fswz(t + 512)] = cmul(y2, tw[2 * e]);
        Zs[fswz(t + 768)] = cmul(y3, tw[3 * e]);
    }
    __syncthreads();

    // stages 1..4
    #pragma unroll
    for (int s = 1; s < 5; s++) {
        const int qsh = 8 - 2 * s;               // quarter = 1<<qsh
        const int quarter = 1 << qsh;
        const int j = t & (quarter - 1);
        const int i0 = ((t >> qsh) << (qsh + 2)) + j;
        const int e = j << (2 * s);
        float2 x0 = Zs[fswz(i0)];
        float2 x1 = Zs[fswz(i0 + quarter)];
        float2 x2 = Zs[fswz(i0 + 2 * quarter)];
        float2 x3 = Zs[fswz(i0 + 3 * quarter)];
        float2 p02 = make_float2(x0.x + x2.x, x0.y + x2.y);
        float2 m02 = make_float2(x0.x - x2.x, x0.y - x2.y);
        float2 p13 = make_float2(x1.x + x3.x, x1.y + x3.y);
        float2 m13 = make_float2(x1.x - x3.x, x1.y - x3.y);
        float2 y0 = make_float2(p02.x + p13.x, p02.y + p13.y);
        float2 y2 = make_float2(p02.x - p13.x, p02.y - p13.y);
        float2 y1 = make_float2(m02.x + m13.y, m02.y - m13.x);
        float2 y3 = make_float2(m02.x - m13.y, m02.y + m13.x);
        __syncthreads();
        Zs[fswz(i0)]               = y0;
        Zs[fswz(i0 + quarter)]     = cmul(y1, tw[e]);
        Zs[fswz(i0 + 2 * quarter)] = cmul(y2, tw[2 * e]);
        Zs[fswz(i0 + 3 * quarter)] = cmul(y3, tw[3 * e]);
        __syncthreads();
    }

    // cross spectrum: Q(f)=(A+conj(B))/2 trick; X[f] sits at fswz(rev4(f))
    for (int f = F0 + t; f <= 512; f += 256) {
        float2 A  = Zs[fswz(rev4(f))];
        float2 Zc = Zs[fswz(rev4(1024 - f))];
        float Br =  Zc.x, Bi = -Zc.y;
        float Ur = A.x + Br, Ui = A.y + Bi;
        float Vr = A.x - Br, Vi = A.y - Bi;
        float Pr = 0.25f * (Ur * Vi - Ui * Vr);
        float Pi = 0.25f * (Ur * Vr + Ui * Vi);
        g_P[(size_t)row * NF + (f - F0)] = make_float2(Pr, Pi);
    }
}

// ---------------- deterministic channel reduction ---------------------------
__global__ void __launch_bounds__(256) reduce_S_kernel()
{
    const int b = blockIdx.x, j = blockIdx.y;
    const int tid = threadIdx.x;
    float2 acc = make_float2(0.f, 0.f);
    for (int r = tid; r < 1024; r += 256) {
        float2 p = g_P[(size_t)((b << 10) + r) * NF + j];
        acc.x += p.x; acc.y += p.y;
    }
    __shared__ float2 sh[256];
    sh[tid] = acc;
    __syncthreads();
    for (int o = 128; o > 0; o >>= 1) {
        if (tid < o) { sh[tid].x += sh[tid + o].x; sh[tid].y += sh[tid + o].y; }
        __syncthreads();
    }
    if (tid == 0) g_S[b][j] = sh[0];
}

// ---------------- irfft of masked spectrum -> mean_value --------------------
__global__ void __launch_bounds__(256) irfft_mean_kernel()
{
    __shared__ float2 tw[1024];
    __shared__ float2 Sb[NF];
    const int b = blockIdx.x;
    const int tid = threadIdx.x;
    for (int j = tid; j < 1024; j += 256) {
        float s, c;
        sincospif((float)j / 512.0f, &s, &c);
        tw[j] = make_float2(c, s);
    }
    for (int j = tid; j < NF; j += 256) Sb[j] = g_S[b][j];
    __syncthreads();

    const int tau = blockIdx.y * 256 + tid;
    float acc = 0.f;
    #pragma unroll 4
    for (int j = 0; j < NF - 1; j++) {
        int id = ((F0 + j) * tau) & 1023;
        float2 s = Sb[j], w = tw[id];
        acc += s.x * w.x - s.y * w.y;
    }
    acc *= 2.0f;
    {
        int id = (512 * tau) & 1023;
        float2 s = Sb[NF - 1], w = tw[id];
        acc += s.x * w.x - s.y * w.y;
    }
    g_mv[b][tau] = acc * (1.0f / (1024.0f * 1024.0f));
}

// ---------------- global top-6 lags + per-batch softmax ---------------------
__global__ void __launch_bounds__(256) topk_kernel()
{
    __shared__ float g[1024];
    __shared__ float rv[256];
    __shared__ int   ri[256];
    __shared__ int   chosen[TOPK];
    const int tid = threadIdx.x;

    for (int t = tid; t < 1024; t += 256) {
        float s = 0.f;
        #pragma unroll
        for (int b = 0; b < BB; b++) s += g_mv[b][t];
        g[t] = s;
    }
    __syncthreads();

    for (int p = 0; p < TOPK; p++) {
        float best = -3.0e38f; int bi = 1 << 30;
        for (int t = tid; t < 1024; t += 256) {
            float v = g[t];
            if (v > best) { best = v; bi = t; }
        }
        rv[tid] = best; ri[tid] = bi;
        __syncthreads();
        for (int o = 128; o > 0; o >>= 1) {
            if (tid < o) {
                float v2 = rv[tid + o]; int i2 = ri[tid + o];
                if (v2 > rv[tid] || (v2 == rv[tid] && i2 < ri[tid])) {
                    rv[tid] = v2; ri[tid] = i2;
                }
            }
            __syncthreads();
        }
        if (tid == 0) { chosen[p] = ri[0]; g[ri[0]] = -3.0e38f; }
        __syncthreads();
    }

    if (tid < BB) {
        int b = tid;
        float w[TOPK], mx = -3.0e38f;
        #pragma unroll
        for (int i = 0; i < TOPK; i++) { w[i] = g_mv[b][chosen[i]]; mx = fmaxf(mx, w[i]); }
        float sum = 0.f;
        #pragma unroll
        for (int i = 0; i < TOPK; i++) { w[i] = expf(w[i] - mx); sum += w[i]; }
        #pragma unroll
        for (int i = 0; i < TOPK; i++) g_tc[b][i] = w[i] / sum;
    }
    if (tid >= 32 && tid < 32 + TOPK) g_idx[tid - 32] = chosen[tid - 32];
}

// ---------------- fused shift-agg + transpose + bf16 split ------------------
// block: (b, c-tile of 32); out ctx_hi/lo[(b*L + t)*HID + c]
#define GT_SMEM (32 * 1025 * 4)
__global__ void __launch_bounds__(256) gatherT_kernel()
{
    extern __shared__ float vs[];            // [32][1025]
    __shared__ int   sh[TOPK];
    __shared__ float w[TOPK];
    const int b  = blockIdx.y;
    const int c0 = blockIdx.x * 32;
    const int tid = threadIdx.x;
    if (tid < TOPK) { sh[tid] = g_idx[tid]; w[tid] = g_tc[b][tid]; }
    for (int idx = tid; idx < 32 * 1024; idx += 256) {
        int r = idx >> 10, t = idx & 1023;
        vs[r * 1025 + t] = g_v[((size_t)(b << 10) + c0 + r) * 1024 + t];
    }
    __syncthreads();
    const int cc = tid & 31;
    for (int tt = tid >> 5; tt < 1024; tt += 8) {
        float a = 0.f;
        #pragma unroll
        for (int i = 0; i < TOPK; i++)
            a += w[i] * vs[cc * 1025 + ((tt + sh[i]) & 1023)];
        size_t pos = ((size_t)(b << 10) + tt) * 1024 + c0 + cc;
        __nv_bfloat16 h, l;
        split1(a, h, l);
        g_ctx_hi[pos] = h;
        g_ctx_lo[pos] = l;
    }
}

// ---------------- residual + LayerNorm --------------------------------------
__global__ void __launch_bounds__(256) ln_kernel(
    const float* __restrict__ x, const float* __restrict__ gamma,
    const float* __restrict__ beta, float* __restrict__ out)
{
    const int m = blockIdx.x;
    const int tid = threadIdx.x;
    const float* h  = g_hidden + (size_t)m * 1024;
    const float* xi = x        + (size_t)m * 1024;

    float v[4];
    float s1 = 0.f, s2 = 0.f;
    #pragma unroll
    for (int i = 0; i < 4; i++) {
        float t = h[tid + 256 * i] + xi[tid + 256 * i];
        v[i] = t; s1 += t; s2 += t * t;
    }
    #pragma unroll
    for (int o = 16; o > 0; o >>= 1) {
        s1 += __shfl_xor_sync(0xffffffffu, s1, o);
        s2 += __shfl_xor_sync(0xffffffffu, s2, o);
    }
    __shared__ float w1[8], w2[8];
    __shared__ float sh_mean, sh_inv;
    const int wid = tid >> 5, lane = tid & 31;
    if (lane == 0) { w1[wid] = s1; w2[wid] = s2; }
    __syncthreads();
    if (tid == 0) {
        float a = 0.f, bq = 0.f;
        #pragma unroll
        for (int i = 0; i < 8; i++) { a += w1[i]; bq += w2[i]; }
        float mean = a * (1.0f / 1024.0f);
        float var  = bq * (1.0f / 1024.0f) - mean * mean;
        sh_mean = mean;
        sh_inv  = rsqrtf(var + 1e-12f);
    }
    __syncthreads();
    const float mean = sh_mean, inv = sh_inv;
    #pragma unroll
    for (int i = 0; i < 4; i++) {
        int c = tid + 256 * i;
        out[(size_t)m * 1024 + c] = (v[i] - mean) * inv * gamma[c] + beta[c];
    }
}

// ---------------- launch ----------------------------------------------------
extern "C" void kernel_launch(void* const* d_in, const int* in_sizes, int n_in,
                              void* d_out, int out_size)
{
    (void)in_sizes; (void)n_in; (void)out_size;
    const float* x     = (const float*)d_in[0];
    const float* Wq    = (const float*)d_in[2];
    const float* bq    = (const float*)d_in[3];
    const float* Wk    = (const float*)d_in[4];
    const float* bk    = (const float*)d_in[5];
    const float* Wv    = (const float*)d_in[6];
    const float* bv    = (const float*)d_in[7];
    const float* Wd    = (const float*)d_in[8];
    const float* bd    = (const float*)d_in[9];
    const float* gamma = (const float*)d_in[10];
    const float* beta  = (const float*)d_in[11];
    float* out = (float*)d_out;

    static bool attr_done = false;
    if (!attr_done) {
        cudaFuncSetAttribute(gemm_bf16,      cudaFuncAttributeMaxDynamicSharedMemorySize, GSMEM);
        cudaFuncSetAttribute(gatherT_kernel, cudaFuncAttributeMaxDynamicSharedMemorySize, GT_SMEM);
        attr_done = true;
    }

    dim3 ggrid(8, 128);   // N/128 x M/128
    split_x_kernel<<<NROW * LL / 1024, 256>>>(x);
    transpose_w<<<dim3(32, 32, 4), 256>>>(Wq, Wk, Wv, Wd);
    gemm_bf16<<<ggrid, 256, GSMEM>>>(bq, 0);
    gemm_bf16<<<ggrid, 256, GSMEM>>>(bk, 1);
    gemm_bf16<<<ggrid, 256, GSMEM>>>(bv, 2);
    fft_corr_kernel<<<NROW, 256>>>();
    reduce_S_kernel<<<dim3(BB, NF), 256>>>();
    irfft_mean_kernel<<<dim3(BB, 4), 256>>>();
    topk_kernel<<<1, 256>>>();
    gatherT_kernel<<<dim3(32, BB), 256, GT_SMEM>>>();
    gemm_bf16<<<ggrid, 256, GSMEM>>>(bd, 3);
    ln_kernel<<<NROW, 256>>>(x, gamma, beta, out);
}

// round 8
// speedup vs baseline: 2.8473x; 1.1099x over previous
#include <cuda_runtime.h>
#include <cuda_bf16.h>
#include <cstdint>

// Problem constants
#define BB   16
#define LL   1024
#define HID  1024
#define NROW (BB * HID)
#define NF   308
#define F0   205
#define TOPK 6

// ---------------- scratch (device globals) ----------------------------------
__device__ float  g_q[NROW * LL];        // (B,HID,L)
__device__ float  g_k[NROW * LL];
__device__ float  g_v[NROW * LL];
__device__ float  g_hidden[NROW * LL];   // (B*L, HID) row-major
__device__ __nv_bfloat16 g_x_hi[NROW * LL];    // x split, (B*L, HID)
__device__ __nv_bfloat16 g_x_lo[NROW * LL];
__device__ __nv_bfloat16 g_wt_hi[4 * HID * HID];  // transposed weights [n][k]
__device__ __nv_bfloat16 g_wt_lo[4 * HID * HID];
__device__ __nv_bfloat16 g_ctx_hi[NROW * LL];     // ctx (B*L, HID)
__device__ __nv_bfloat16 g_ctx_lo[NROW * LL];
__device__ float2 g_P[NROW * NF];
__device__ float2 g_S[BB][NF];
__device__ float  g_mv[BB][LL];
__device__ int    g_idx[TOPK];
__device__ float  g_tc[BB][TOPK];

// ---------------- split helpers ---------------------------------------------
__device__ __forceinline__ void split1(float x, __nv_bfloat16& h, __nv_bfloat16& l) {
    h = __float2bfloat16(x);
    l = __float2bfloat16(x - __bfloat162float(h));
}

// x -> bf16 hi/lo (done once; feeds all 3 QKV GEMMs)
__global__ void __launch_bounds__(256) split_x_kernel(const float* __restrict__ x)
{
    size_t i = ((size_t)blockIdx.x * 256 + threadIdx.x) * 4;
    float4 v = *(const float4*)&x[i];
    __nv_bfloat16 h0, l0, h1, l1, h2, l2, h3, l3;
    split1(v.x, h0, l0); split1(v.y, h1, l1);
    split1(v.z, h2, l2); split1(v.w, h3, l3);
    __nv_bfloat162 hh01 = {h0, h1}, hh23 = {h2, h3};
    __nv_bfloat162 ll01 = {l0, l1}, ll23 = {l2, l3};
    uint2 hi, lo;
    hi.x = *(unsigned*)&hh01; hi.y = *(unsigned*)&hh23;
    lo.x = *(unsigned*)&ll01; lo.y = *(unsigned*)&ll23;
    *(uint2*)&g_x_hi[i] = hi;
    *(uint2*)&g_x_lo[i] = lo;
}

// ---------------- weight transpose + split ----------------------------------
__global__ void __launch_bounds__(256) transpose_w(
    const float* __restrict__ W0, const float* __restrict__ W1,
    const float* __restrict__ W2, const float* __restrict__ W3)
{
    __shared__ float tile[32][33];
    const float* src = (blockIdx.z == 0) ? W0 : (blockIdx.z == 1) ? W1
                     : (blockIdx.z == 2) ? W2 : W3;
    __nv_bfloat16* dh = g_wt_hi + (size_t)blockIdx.z * HID * HID;
    __nv_bfloat16* dl = g_wt_lo + (size_t)blockIdx.z * HID * HID;
    const int tx = threadIdx.x & 31, ty = threadIdx.x >> 5;   // 32 x 8
    const int x  = blockIdx.x * 32 + tx;
    const int y0 = blockIdx.y * 32;
    #pragma unroll
    for (int j = 0; j < 32; j += 8)
        tile[ty + j][tx] = src[(size_t)(y0 + ty + j) * HID + x];
    __syncthreads();
    const int x2 = y0 + tx;
    const int y2 = blockIdx.x * 32;
    #pragma unroll
    for (int j = 0; j < 32; j += 8) {
        float v = tile[tx][ty + j];
        __nv_bfloat16 h, l;
        split1(v, h, l);
        dh[(size_t)(y2 + ty + j) * HID + x2] = h;
        dl[(size_t)(y2 + ty + j) * HID + x2] = l;
    }
}

// ---------------- bf16-split GEMM, cp.async 3-stage pipeline ----------------
// smem per stage: 4 arrays (Ahi, Alo, Bhi, Blo), each 128 rows x 64B,
// 16B chunks XOR-swizzled: chunk' = chunk ^ ((row>>1)&3)
#define ARRB   8192                   // 128 * 64
#define STAGEB (4 * ARRB)             // 32768
#define GSMEM  (3 * STAGEB)           // 98304

__device__ __forceinline__ void mma_bf16(float* c, const unsigned* a, const unsigned* b) {
    asm volatile(
        "mma.sync.aligned.m16n8k16.row.col.f32.bf16.bf16.f32 "
        "{%0,%1,%2,%3}, {%4,%5,%6,%7}, {%8,%9}, {%0,%1,%2,%3};"
        : "+f"(c[0]), "+f"(c[1]), "+f"(c[2]), "+f"(c[3])
        : "r"(a[0]), "r"(a[1]), "r"(a[2]), "r"(a[3]), "r"(b[0]), "r"(b[1]));
}
__device__ __forceinline__ void ldsm4(unsigned* r, uint32_t addr) {
    asm volatile("ldmatrix.sync.aligned.m8n8.x4.shared.b16 {%0,%1,%2,%3}, [%4];"
        : "=r"(r[0]), "=r"(r[1]), "=r"(r[2]), "=r"(r[3]) : "r"(addr));
}
__device__ __forceinline__ void cpasync16(uint32_t dst, const void* src) {
    asm volatile("cp.async.cg.shared.global [%0], [%1], 16;" :: "r"(dst), "l"(src));
}

__device__ __forceinline__ void issue_stage(
    uint32_t sb,
    const __nv_bfloat16* __restrict__ Ah, const __nv_bfloat16* __restrict__ Al,
    const __nv_bfloat16* __restrict__ Bh, const __nv_bfloat16* __restrict__ Bl,
    int m0, int n0, int k0, int tid)
{
    #pragma unroll
    for (int c = 0; c < 2; c++) {
        int chunk = tid + c * 256;
        int row = chunk >> 2, ch = chunk & 3;
        uint32_t so = (uint32_t)row * 64 + (uint32_t)((ch ^ ((row >> 1) & 3)) << 4);
        size_t ga = (size_t)(m0 + row) * 1024 + k0 + ch * 8;
        size_t gb = (size_t)(n0 + row) * 1024 + k0 + ch * 8;
        cpasync16(sb + so,            Ah + ga);
        cpasync16(sb + ARRB + so,     Al + ga);
        cpasync16(sb + 2 * ARRB + so, Bh + gb);
        cpasync16(sb + 3 * ARRB + so, Bl + gb);
    }
}

// mode 0: fused QKV (which = blockIdx.z); mode 3: output projection
__global__ void __launch_bounds__(256, 2) gemm_bf16(
    const float* __restrict__ b0p, const float* __restrict__ b1p,
    const float* __restrict__ b2p, int mode)
{
    extern __shared__ char smem[];
    const uint32_t sbase = (uint32_t)__cvta_generic_to_shared(smem);

    const int which = (mode == 0) ? (int)blockIdx.z : 3;
    const float* bias = (which == 0) ? b0p : (which == 1) ? b1p : (which == 2) ? b2p : b0p;
    const __nv_bfloat16* Ah = (which == 3) ? g_ctx_hi : g_x_hi;
    const __nv_bfloat16* Al = (which == 3) ? g_ctx_lo : g_x_lo;
    const __nv_bfloat16* Bh = g_wt_hi + (size_t)which * HID * HID;
    const __nv_bfloat16* Bl = g_wt_lo + (size_t)which * HID * HID;
    float* Out = (which == 0) ? g_q : (which == 1) ? g_k
               : (which == 2) ? g_v : g_hidden;

    const int m0 = blockIdx.y * 128;
    const int n0 = blockIdx.x * 128;
    const int tid  = threadIdx.x;
    const int lane = tid & 31;
    const int wid  = tid >> 5;
    const int wm = wid & 1;
    const int wn = wid >> 1;
    const int gid = lane >> 2;
    const int tig = lane & 3;

    // ldmatrix per-lane bases
    const int a_rowb = wm * 64 + ((lane >> 3) & 1) * 8 + (lane & 7);  // + mi*16
    const int a_cbit = (lane >> 4) & 1;
    const int b_rowb = wn * 32 + ((lane >> 4) & 1) * 8 + (lane & 7);  // + pi*16
    const int b_cbit = (lane >> 3) & 1;

    uint32_t a_rb[4], b_rb[2];
    int a_swz[4], b_swz[2];
    #pragma unroll
    for (int mi = 0; mi < 4; mi++) {
        int r = a_rowb + mi * 16;
        a_rb[mi] = (uint32_t)r * 64;
        a_swz[mi] = (r >> 1) & 3;
    }
    #pragma unroll
    for (int pi = 0; pi < 2; pi++) {
        int r = b_rowb + pi * 16;
        b_rb[pi] = (uint32_t)r * 64;
        b_swz[pi] = (r >> 1) & 3;
    }

    float c[4][4][4];
    #pragma unroll
    for (int i = 0; i < 4; i++)
        #pragma unroll
        for (int j = 0; j < 4; j++)
            #pragma unroll
            for (int r = 0; r < 4; r++) c[i][j][r] = 0.f;

    // prologue: prefetch stages 0..1
    issue_stage(sbase + 0 * STAGEB, Ah, Al, Bh, Bl, m0, n0, 0,  tid);
    asm volatile("cp.async.commit_group;");
    issue_stage(sbase + 1 * STAGEB, Ah, Al, Bh, Bl, m0, n0, 32, tid);
    asm volatile("cp.async.commit_group;");

    int buf = 0, nbuf = 2;
    for (int kt = 0; kt < 32; kt++) {
        asm volatile("cp.async.wait_group 1;");
        __syncthreads();

        if (kt + 2 < 32)
            issue_stage(sbase + (uint32_t)nbuf * STAGEB, Ah, Al, Bh, Bl,
                        m0, n0, (kt + 2) * 32, tid);
        asm volatile("cp.async.commit_group;");

        const uint32_t sb = sbase + (uint32_t)buf * STAGEB;
        #pragma unroll
        for (int ks = 0; ks < 2; ks++) {
            unsigned ah[4][4], al[4][4], bh[4][2], bl[4][2];
            const int cbase = ks * 2;
            #pragma unroll
            for (int mi = 0; mi < 4; mi++) {
                uint32_t ad = sb + a_rb[mi]
                            + (uint32_t)((((cbase | a_cbit) ^ a_swz[mi]) << 4));
                ldsm4(ah[mi], ad);
                ldsm4(al[mi], ad + ARRB);
            }
            #pragma unroll
            for (int pi = 0; pi < 2; pi++) {
                uint32_t bd = sb + 2 * ARRB + b_rb[pi]
                            + (uint32_t)((((cbase | b_cbit) ^ b_swz[pi]) << 4));
                unsigned tmp[4];
                ldsm4(tmp, bd);
                bh[2 * pi][0] = tmp[0]; bh[2 * pi][1] = tmp[1];
                bh[2 * pi + 1][0] = tmp[2]; bh[2 * pi + 1][1] = tmp[3];
                ldsm4(tmp, bd + ARRB);
                bl[2 * pi][0] = tmp[0]; bl[2 * pi][1] = tmp[1];
                bl[2 * pi + 1][0] = tmp[2]; bl[2 * pi + 1][1] = tmp[3];
            }
            #pragma unroll
            for (int mi = 0; mi < 4; mi++)
                #pragma unroll
                for (int ni = 0; ni < 4; ni++) {
                    mma_bf16(c[mi][ni], ah[mi], bh[ni]);
                    mma_bf16(c[mi][ni], ah[mi], bl[ni]);
                    mma_bf16(c[mi][ni], al[mi], bh[ni]);
                }
        }
        buf = (buf == 2) ? 0 : buf + 1;
        nbuf = (nbuf == 2) ? 0 : nbuf + 1;
    }

    // epilogue
    if (which < 3) {
        const int bidx = m0 >> 10;
        #pragma unroll
        for (int mi = 0; mi < 4; mi++) {
            #pragma unroll
            for (int r = 0; r < 2; r++) {
                int m = m0 + wm * 64 + mi * 16 + gid + r * 8;
                int t = m & 1023;
                #pragma unroll
                for (int ni = 0; ni < 4; ni++) {
                    int nb = n0 + wn * 32 + ni * 8 + 2 * tig;
                    float v0 = c[mi][ni][r * 2 + 0] + bias[nb];
                    float v1 = c[mi][ni][r * 2 + 1] + bias[nb + 1];
                    Out[(((size_t)(bidx << 10) + nb) << 10) + t] = v0;
                    Out[(((size_t)(bidx << 10) + nb + 1) << 10) + t] = v1;
                }
            }
        }
    } else {
        #pragma unroll
        for (int mi = 0; mi < 4; mi++) {
            #pragma unroll
            for (int r = 0; r < 2; r++) {
                int m = m0 + wm * 64 + mi * 16 + gid + r * 8;
                #pragma unroll
                for (int ni = 0; ni < 4; ni++) {
                    int nb = n0 + wn * 32 + ni * 8 + 2 * tig;
                    float2 v;
                    v.x = c[mi][ni][r * 2 + 0] + bias[nb];
                    v.y = c[mi][ni][r * 2 + 1] + bias[nb + 1];
                    *(float2*)&Out[(size_t)m * 1024 + nb] = v;
                }
            }
        }
    }
}

// ---------------- radix-4 DIF FFT + cross spectrum --------------------------
__device__ __forceinline__ int fswz(int p) { return p ^ ((p >> 2) & 15); }
__device__ __forceinline__ int rev4(int x) {
    return ((x & 3) << 8) | (((x >> 2) & 3) << 6) | (((x >> 4) & 3) << 4)
         | (((x >> 6) & 3) << 2) | ((x >> 8) & 3);
}
__device__ __forceinline__ float2 cmul(float2 a, float2 w) {
    return make_float2(a.x * w.x - a.y * w.y, a.x * w.y + a.y * w.x);
}

__global__ void __launch_bounds__(256) fft_corr_kernel()
{
    __shared__ float2 Zs[1024];
    __shared__ float2 tw[1024];
    const int row = blockIdx.x;
    const int t = threadIdx.x;
    const float* qr = g_q + (size_t)row * 1024;
    const float* kr = g_k + (size_t)row * 1024;

    for (int j = t; j < 1024; j += 256) {
        float s, c;
        sincospif(-(float)j / 512.0f, &s, &c);
        tw[j] = make_float2(c, s);
    }
    __syncthreads();

    {
        float2 x0 = make_float2(qr[t],       kr[t]);
        float2 x1 = make_float2(qr[t + 256], kr[t + 256]);
        float2 x2 = make_float2(qr[t + 512], kr[t + 512]);
        float2 x3 = make_float2(qr[t + 768], kr[t + 768]);
        float2 p02 = make_float2(x0.x + x2.x, x0.y + x2.y);
        float2 m02 = make_float2(x0.x - x2.x, x0.y - x2.y);
        float2 p13 = make_float2(x1.x + x3.x, x1.y + x3.y);
        float2 m13 = make_float2(x1.x - x3.x, x1.y - x3.y);
        float2 y0 = make_float2(p02.x + p13.x, p02.y + p13.y);
        float2 y2 = make_float2(p02.x - p13.x, p02.y - p13.y);
        float2 y1 = make_float2(m02.x + m13.y, m02.y - m13.x);
        float2 y3 = make_float2(m02.x - m13.y, m02.y + m13.x);
        int e = t;
        Zs[fswz(t)]       = y0;
        Zs[fswz(t + 256)] = cmul(y1, tw[e]);
        Zs[fswz(t + 512)] = cmul(y2, tw[2 * e]);
        Zs[fswz(t + 768)] = cmul(y3, tw[3 * e]);
    }
    __syncthreads();

    #pragma unroll
    for (int s = 1; s < 5; s++) {
        const int qsh = 8 - 2 * s;
        const int quarter = 1 << qsh;
        const int j = t & (quarter - 1);
        const int i0 = ((t >> qsh) << (qsh + 2)) + j;
        const int e = j << (2 * s);
        float2 x0 = Zs[fswz(i0)];
        float2 x1 = Zs[fswz(i0 + quarter)];
        float2 x2 = Zs[fswz(i0 + 2 * quarter)];
        float2 x3 = Zs[fswz(i0 + 3 * quarter)];
        float2 p02 = make_float2(x0.x + x2.x, x0.y + x2.y);
        float2 m02 = make_float2(x0.x - x2.x, x0.y - x2.y);
        float2 p13 = make_float2(x1.x + x3.x, x1.y + x3.y);
        float2 m13 = make_float2(x1.x - x3.x, x1.y - x3.y);
        float2 y0 = make_float2(p02.x + p13.x, p02.y + p13.y);
        float2 y2 = make_float2(p02.x - p13.x, p02.y - p13.y);
        float2 y1 = make_float2(m02.x + m13.y, m02.y - m13.x);
        float2 y3 = make_float2(m02.x - m13.y, m02.y + m13.x);
        __syncthreads();
        Zs[fswz(i0)]               = y0;
        Zs[fswz(i0 + quarter)]     = cmul(y1, tw[e]);
        Zs[fswz(i0 + 2 * quarter)] = cmul(y2, tw[2 * e]);
        Zs[fswz(i0 + 3 * quarter)] = cmul(y3, tw[3 * e]);
        __syncthreads();
    }

    for (int f = F0 + t; f <= 512; f += 256) {
        float2 A  = Zs[fswz(rev4(f))];
        float2 Zc = Zs[fswz(rev4(1024 - f))];
        float Br =  Zc.x, Bi = -Zc.y;
        float Ur = A.x + Br, Ui = A.y + Bi;
        float Vr = A.x - Br, Vi = A.y - Bi;
        float Pr = 0.25f * (Ur * Vi - Ui * Vr);
        float Pi = 0.25f * (Ur * Vr + Ui * Vi);
        g_P[(size_t)row * NF + (f - F0)] = make_float2(Pr, Pi);
    }
}

// ---------------- deterministic channel reduction ---------------------------
__global__ void __launch_bounds__(256) reduce_S_kernel()
{
    const int b = blockIdx.x, j = blockIdx.y;
    const int tid = threadIdx.x;
    float2 acc = make_float2(0.f, 0.f);
    for (int r = tid; r < 1024; r += 256) {
        float2 p = g_P[(size_t)((b << 10) + r) * NF + j];
        acc.x += p.x; acc.y += p.y;
    }
    __shared__ float2 sh[256];
    sh[tid] = acc;
    __syncthreads();
    for (int o = 128; o > 0; o >>= 1) {
        if (tid < o) { sh[tid].x += sh[tid + o].x; sh[tid].y += sh[tid + o].y; }
        __syncthreads();
    }
    if (tid == 0) g_S[b][j] = sh[0];
}

// ---------------- irfft of masked spectrum -> mean_value --------------------
__global__ void __launch_bounds__(256) irfft_mean_kernel()
{
    __shared__ float2 tw[1024];
    __shared__ float2 Sb[NF];
    const int b = blockIdx.x;
    const int tid = threadIdx.x;
    for (int j = tid; j < 1024; j += 256) {
        float s, c;
        sincospif((float)j / 512.0f, &s, &c);
        tw[j] = make_float2(c, s);
    }
    for (int j = tid; j < NF; j += 256) Sb[j] = g_S[b][j];
    __syncthreads();

    const int tau = blockIdx.y * 256 + tid;
    float acc = 0.f;
    #pragma unroll 4
    for (int j = 0; j < NF - 1; j++) {
        int id = ((F0 + j) * tau) & 1023;
        float2 s = Sb[j], w = tw[id];
        acc += s.x * w.x - s.y * w.y;
    }
    acc *= 2.0f;
    {
        int id = (512 * tau) & 1023;
        float2 s = Sb[NF - 1], w = tw[id];
        acc += s.x * w.x - s.y * w.y;
    }
    g_mv[b][tau] = acc * (1.0f / (1024.0f * 1024.0f));
}

// ---------------- global top-6 lags + per-batch softmax ---------------------
__global__ void __launch_bounds__(256) topk_kernel()
{
    __shared__ float g[1024];
    __shared__ float rv[256];
    __shared__ int   ri[256];
    __shared__ int   chosen[TOPK];
    const int tid = threadIdx.x;

    for (int t = tid; t < 1024; t += 256) {
        float s = 0.f;
        #pragma unroll
        for (int b = 0; b < BB; b++) s += g_mv[b][t];
        g[t] = s;
    }
    __syncthreads();

    for (int p = 0; p < TOPK; p++) {
        float best = -3.0e38f; int bi = 1 << 30;
        for (int t = tid; t < 1024; t += 256) {
            float v = g[t];
            if (v > best) { best = v; bi = t; }
        }
        rv[tid] = best; ri[tid] = bi;
        __syncthreads();
        for (int o = 128; o > 0; o >>= 1) {
            if (tid < o) {
                float v2 = rv[tid + o]; int i2 = ri[tid + o];
                if (v2 > rv[tid] || (v2 == rv[tid] && i2 < ri[tid])) {
                    rv[tid] = v2; ri[tid] = i2;
                }
            }
            __syncthreads();
        }
        if (tid == 0) { chosen[p] = ri[0]; g[ri[0]] = -3.0e38f; }
        __syncthreads();
    }

    if (tid < BB) {
        int b = tid;
        float w[TOPK], mx = -3.0e38f;
        #pragma unroll
        for (int i = 0; i < TOPK; i++) { w[i] = g_mv[b][chosen[i]]; mx = fmaxf(mx, w[i]); }
        float sum = 0.f;
        #pragma unroll
        for (int i = 0; i < TOPK; i++) { w[i] = expf(w[i] - mx); sum += w[i]; }
        #pragma unroll
        for (int i = 0; i < TOPK; i++) g_tc[b][i] = w[i] / sum;
    }
    if (tid >= 32 && tid < 32 + TOPK) g_idx[tid - 32] = chosen[tid - 32];
}

// ---------------- fused shift-agg + transpose + bf16 split ------------------
#define GT_SMEM (32 * 1025 * 4)
__global__ void __launch_bounds__(256) gatherT_kernel()
{
    extern __shared__ float vs[];            // [32][1025]
    __shared__ int   sh[TOPK];
    __shared__ float w[TOPK];
    const int b  = blockIdx.y;
    const int c0 = blockIdx.x * 32;
    const int tid = threadIdx.x;
    if (tid < TOPK) { sh[tid] = g_idx[tid]; w[tid] = g_tc[b][tid]; }
    for (int idx = tid; idx < 32 * 1024; idx += 256) {
        int r = idx >> 10, t = idx & 1023;
        vs[r * 1025 + t] = g_v[((size_t)(b << 10) + c0 + r) * 1024 + t];
    }
    __syncthreads();
    const int cc = tid & 31;
    for (int tt = tid >> 5; tt < 1024; tt += 8) {
        float a = 0.f;
        #pragma unroll
        for (int i = 0; i < TOPK; i++)
            a += w[i] * vs[cc * 1025 + ((tt + sh[i]) & 1023)];
        size_t pos = ((size_t)(b << 10) + tt) * 1024 + c0 + cc;
        __nv_bfloat16 h, l;
        split1(a, h, l);
        g_ctx_hi[pos] = h;
        g_ctx_lo[pos] = l;
    }
}

// ---------------- residual + LayerNorm --------------------------------------
__global__ void __launch_bounds__(256) ln_kernel(
    const float* __restrict__ x, const float* __restrict__ gamma,
    const float* __restrict__ beta, float* __restrict__ out)
{
    const int m = blockIdx.x;
    const int tid = threadIdx.x;
    const float* h  = g_hidden + (size_t)m * 1024;
    const float* xi = x        + (size_t)m * 1024;

    float v[4];
    float s1 = 0.f, s2 = 0.f;
    #pragma unroll
    for (int i = 0; i < 4; i++) {
        float t = h[tid + 256 * i] + xi[tid + 256 * i];
        v[i] = t; s1 += t; s2 += t * t;
    }
    #pragma unroll
    for (int o = 16; o > 0; o >>= 1) {
        s1 += __shfl_xor_sync(0xffffffffu, s1, o);
        s2 += __shfl_xor_sync(0xffffffffu, s2, o);
    }
    __shared__ float w1[8], w2[8];
    __shared__ float sh_mean, sh_inv;
    const int wid = tid >> 5, lane = tid & 31;
    if (lane == 0) { w1[wid] = s1; w2[wid] = s2; }
    __syncthreads();
    if (tid == 0) {
        float a = 0.f, bq = 0.f;
        #pragma unroll
        for (int i = 0; i < 8; i++) { a += w1[i]; bq += w2[i]; }
        float mean = a * (1.0f / 1024.0f);
        float var  = bq * (1.0f / 1024.0f) - mean * mean;
        sh_mean = mean;
        sh_inv  = rsqrtf(var + 1e-12f);
    }
    __syncthreads();
    const float mean = sh_mean, inv = sh_inv;
    #pragma unroll
    for (int i = 0; i < 4; i++) {
        int c = tid + 256 * i;
        out[(size_t)m * 1024 + c] = (v[i] - mean) * inv * gamma[c] + beta[c];
    }
}

// ---------------- launch ----------------------------------------------------
extern "C" void kernel_launch(void* const* d_in, const int* in_sizes, int n_in,
                              void* d_out, int out_size)
{
    (void)in_sizes; (void)n_in; (void)out_size;
    const float* x     = (const float*)d_in[0];
    const float* Wq    = (const float*)d_in[2];
    const float* bq    = (const float*)d_in[3];
    const float* Wk    = (const float*)d_in[4];
    const float* bk    = (const float*)d_in[5];
    const float* Wv    = (const float*)d_in[6];
    const float* bv    = (const float*)d_in[7];
    const float* Wd    = (const float*)d_in[8];
    const float* bd    = (const float*)d_in[9];
    const float* gamma = (const float*)d_in[10];
    const float* beta  = (const float*)d_in[11];
    float* out = (float*)d_out;

    static bool attr_done = false;
    if (!attr_done) {
        cudaFuncSetAttribute(gemm_bf16,      cudaFuncAttributeMaxDynamicSharedMemorySize, GSMEM);
        cudaFuncSetAttribute(gatherT_kernel, cudaFuncAttributeMaxDynamicSharedMemorySize, GT_SMEM);
        attr_done = true;
    }

    split_x_kernel<<<NROW * LL / 1024, 256>>>(x);
    transpose_w<<<dim3(32, 32, 4), 256>>>(Wq, Wk, Wv, Wd);
    gemm_bf16<<<dim3(8, 128, 3), 256, GSMEM>>>(bq, bk, bv, 0);     // fused QKV
    fft_corr_kernel<<<NROW, 256>>>();
    reduce_S_kernel<<<dim3(BB, NF), 256>>>();
    irfft_mean_kernel<<<dim3(BB, 4), 256>>>();
    topk_kernel<<<1, 256>>>();
    gatherT_kernel<<<dim3(32, BB), 256, GT_SMEM>>>();
    gemm_bf16<<<dim3(8, 128, 1), 256, GSMEM>>>(bd, bd, bd, 3);     // output proj
    ln_kernel<<<NROW, 256>>>(x, gamma, beta, out);
}

// round 11
// speedup vs baseline: 2.8564x; 1.0032x over previous
#include <cuda_runtime.h>
#include <cuda_bf16.h>
#include <cstdint>

// Problem constants
#define BB   16
#define LL   1024
#define HID  1024
#define NROW (BB * HID)
#define NF   308
#define F0   205
#define TOPK 6

// ---------------- scratch (device globals) ----------------------------------
__device__ float  g_q[NROW * LL];        // (B,HID,L)
__device__ float  g_k[NROW * LL];
__device__ float  g_v[NROW * LL];
__device__ float  g_hidden[NROW * LL];   // (B*L, HID) row-major
__device__ __nv_bfloat16 g_x_hi[NROW * LL];    // x split, (B*L, HID)
__device__ __nv_bfloat16 g_x_lo[NROW * LL];
__device__ __nv_bfloat16 g_wt_hi[4 * HID * HID];  // transposed weights [n][k]
__device__ __nv_bfloat16 g_wt_lo[4 * HID * HID];
__device__ __nv_bfloat16 g_ctx_hi[NROW * LL];     // ctx (B*L, HID)
__device__ __nv_bfloat16 g_ctx_lo[NROW * LL];
__device__ float2 g_P[NROW * NF];
__device__ float2 g_S[BB][NF];
__device__ float  g_mv[BB][LL];
__device__ int    g_idx[TOPK];
__device__ float  g_tc[BB][TOPK];

// ---------------- split helpers ---------------------------------------------
__device__ __forceinline__ void split1(float x, __nv_bfloat16& h, __nv_bfloat16& l) {
    h = __float2bfloat16(x);
    l = __float2bfloat16(x - __bfloat162float(h));
}

// x -> bf16 hi/lo (done once; feeds all 3 QKV GEMMs)
__global__ void __launch_bounds__(256) split_x_kernel(const float* __restrict__ x)
{
    size_t i = ((size_t)blockIdx.x * 256 + threadIdx.x) * 4;
    float4 v = *(const float4*)&x[i];
    __nv_bfloat16 h0, l0, h1, l1, h2, l2, h3, l3;
    split1(v.x, h0, l0); split1(v.y, h1, l1);
    split1(v.z, h2, l2); split1(v.w, h3, l3);
    __nv_bfloat162 hh01 = {h0, h1}, hh23 = {h2, h3};
    __nv_bfloat162 ll01 = {l0, l1}, ll23 = {l2, l3};
    uint2 hi, lo;
    hi.x = *(unsigned*)&hh01; hi.y = *(unsigned*)&hh23;
    lo.x = *(unsigned*)&ll01; lo.y = *(unsigned*)&ll23;
    *(uint2*)&g_x_hi[i] = hi;
    *(uint2*)&g_x_lo[i] = lo;
}

// ---------------- weight transpose + split ----------------------------------
__global__ void __launch_bounds__(256) transpose_w(
    const float* __restrict__ W0, const float* __restrict__ W1,
    const float* __restrict__ W2, const float* __restrict__ W3)
{
    __shared__ float tile[32][33];
    const float* src = (blockIdx.z == 0) ? W0 : (blockIdx.z == 1) ? W1
                     : (blockIdx.z == 2) ? W2 : W3;
    __nv_bfloat16* dh = g_wt_hi + (size_t)blockIdx.z * HID * HID;
    __nv_bfloat16* dl = g_wt_lo + (size_t)blockIdx.z * HID * HID;
    const int tx = threadIdx.x & 31, ty = threadIdx.x >> 5;   // 32 x 8
    const int x  = blockIdx.x * 32 + tx;
    const int y0 = blockIdx.y * 32;
    #pragma unroll
    for (int j = 0; j < 32; j += 8)
        tile[ty + j][tx] = src[(size_t)(y0 + ty + j) * HID + x];
    __syncthreads();
    const int x2 = y0 + tx;
    const int y2 = blockIdx.x * 32;
    #pragma unroll
    for (int j = 0; j < 32; j += 8) {
        float v = tile[tx][ty + j];
        __nv_bfloat16 h, l;
        split1(v, h, l);
        dh[(size_t)(y2 + ty + j) * HID + x2] = h;
        dl[(size_t)(y2 + ty + j) * HID + x2] = l;
    }
}

// ---------------- bf16-split GEMM, cp.async 3-stage pipeline ----------------
// smem per stage: 4 arrays (Ahi, Alo, Bhi, Blo), each 128 rows x 64B,
// 16B chunks XOR-swizzled: chunk' = chunk ^ ((row>>1)&3)
#define ARRB   8192                   // 128 * 64
#define STAGEB (4 * ARRB)             // 32768
#define GSMEM  (3 * STAGEB)           // 98304

__device__ __forceinline__ void mma_bf16(float* c, const unsigned* a, const unsigned* b) {
    asm volatile(
        "mma.sync.aligned.m16n8k16.row.col.f32.bf16.bf16.f32 "
        "{%0,%1,%2,%3}, {%4,%5,%6,%7}, {%8,%9}, {%0,%1,%2,%3};"
        : "+f"(c[0]), "+f"(c[1]), "+f"(c[2]), "+f"(c[3])
        : "r"(a[0]), "r"(a[1]), "r"(a[2]), "r"(a[3]), "r"(b[0]), "r"(b[1]));
}
__device__ __forceinline__ void ldsm4(unsigned* r, uint32_t addr) {
    asm volatile("ldmatrix.sync.aligned.m8n8.x4.shared.b16 {%0,%1,%2,%3}, [%4];"
        : "=r"(r[0]), "=r"(r[1]), "=r"(r[2]), "=r"(r[3]) : "r"(addr));
}
__device__ __forceinline__ void cpasync16(uint32_t dst, const void* src) {
    asm volatile("cp.async.cg.shared.global [%0], [%1], 16;" :: "r"(dst), "l"(src));
}

__device__ __forceinline__ void issue_stage(
    uint32_t sb,
    const __nv_bfloat16* __restrict__ Ah, const __nv_bfloat16* __restrict__ Al,
    const __nv_bfloat16* __restrict__ Bh, const __nv_bfloat16* __restrict__ Bl,
    int m0, int n0, int k0, int tid)
{
    #pragma unroll
    for (int c = 0; c < 2; c++) {
        int chunk = tid + c * 256;
        int row = chunk >> 2, ch = chunk & 3;
        uint32_t so = (uint32_t)row * 64 + (uint32_t)((ch ^ ((row >> 1) & 3)) << 4);
        size_t ga = (size_t)(m0 + row) * 1024 + k0 + ch * 8;
        size_t gb = (size_t)(n0 + row) * 1024 + k0 + ch * 8;
        cpasync16(sb + so,            Ah + ga);
        cpasync16(sb + ARRB + so,     Al + ga);
        cpasync16(sb + 2 * ARRB + so, Bh + gb);
        cpasync16(sb + 3 * ARRB + so, Bl + gb);
    }
}

// mode 0: fused QK (which = blockIdx.z: 0,1); mode 2: V; mode 3: out proj
__global__ void __launch_bounds__(256, 2) gemm_bf16(
    const float* __restrict__ b0p, const float* __restrict__ b1p,
    const float* __restrict__ b2p, int mode)
{
    extern __shared__ char smem[];
    const uint32_t sbase = (uint32_t)__cvta_generic_to_shared(smem);

    const int which = (mode == 0) ? (int)blockIdx.z : mode;
    const float* bias = (which == 0) ? b0p : (which == 1) ? b1p : (which == 2) ? b2p : b0p;
    const __nv_bfloat16* Ah = (which == 3) ? g_ctx_hi : g_x_hi;
    const __nv_bfloat16* Al = (which == 3) ? g_ctx_lo : g_x_lo;
    const __nv_bfloat16* Bh = g_wt_hi + (size_t)which * HID * HID;
    const __nv_bfloat16* Bl = g_wt_lo + (size_t)which * HID * HID;
    float* Out = (which == 0) ? g_q : (which == 1) ? g_k
               : (which == 2) ? g_v : g_hidden;

    const int m0 = blockIdx.y * 128;
    const int n0 = blockIdx.x * 128;
    const int tid  = threadIdx.x;
    const int lane = tid & 31;
    const int wid  = tid >> 5;
    const int wm = wid & 1;
    const int wn = wid >> 1;
    const int gid = lane >> 2;
    const int tig = lane & 3;

    // ldmatrix per-lane bases
    const int a_rowb = wm * 64 + ((lane >> 3) & 1) * 8 + (lane & 7);  // + mi*16
    const int a_cbit = (lane >> 4) & 1;
    const int b_rowb = wn * 32 + ((lane >> 4) & 1) * 8 + (lane & 7);  // + pi*16
    const int b_cbit = (lane >> 3) & 1;

    uint32_t a_rb[4], b_rb[2];
    int a_swz[4], b_swz[2];
    #pragma unroll
    for (int mi = 0; mi < 4; mi++) {
        int r = a_rowb + mi * 16;
        a_rb[mi] = (uint32_t)r * 64;
        a_swz[mi] = (r >> 1) & 3;
    }
    #pragma unroll
    for (int pi = 0; pi < 2; pi++) {
        int r = b_rowb + pi * 16;
        b_rb[pi] = (uint32_t)r * 64;
        b_swz[pi] = (r >> 1) & 3;
    }

    float c[4][4][4];
    #pragma unroll
    for (int i = 0; i < 4; i++)
        #pragma unroll
        for (int j = 0; j < 4; j++)
            #pragma unroll
            for (int r = 0; r < 4; r++) c[i][j][r] = 0.f;

    // prologue: prefetch stages 0..1
    issue_stage(sbase + 0 * STAGEB, Ah, Al, Bh, Bl, m0, n0, 0,  tid);
    asm volatile("cp.async.commit_group;");
    issue_stage(sbase + 1 * STAGEB, Ah, Al, Bh, Bl, m0, n0, 32, tid);
    asm volatile("cp.async.commit_group;");

    int buf = 0, nbuf = 2;
    for (int kt = 0; kt < 32; kt++) {
        asm volatile("cp.async.wait_group 1;");
        __syncthreads();

        if (kt + 2 < 32)
            issue_stage(sbase + (uint32_t)nbuf * STAGEB, Ah, Al, Bh, Bl,
                        m0, n0, (kt + 2) * 32, tid);
        asm volatile("cp.async.commit_group;");

        const uint32_t sb = sbase + (uint32_t)buf * STAGEB;
        #pragma unroll
        for (int ks = 0; ks < 2; ks++) {
            unsigned ah[4][4], al[4][4], bh[4][2], bl[4][2];
            const int cbase = ks * 2;
            #pragma unroll
            for (int mi = 0; mi < 4; mi++) {
                uint32_t ad = sb + a_rb[mi]
                            + (uint32_t)((((cbase | a_cbit) ^ a_swz[mi]) << 4));
                ldsm4(ah[mi], ad);
                ldsm4(al[mi], ad + ARRB);
            }
            #pragma unroll
            for (int pi = 0; pi < 2; pi++) {
                uint32_t bd = sb + 2 * ARRB + b_rb[pi]
                            + (uint32_t)((((cbase | b_cbit) ^ b_swz[pi]) << 4));
                unsigned tmp[4];
                ldsm4(tmp, bd);
                bh[2 * pi][0] = tmp[0]; bh[2 * pi][1] = tmp[1];
                bh[2 * pi + 1][0] = tmp[2]; bh[2 * pi + 1][1] = tmp[3];
                ldsm4(tmp, bd + ARRB);
                bl[2 * pi][0] = tmp[0]; bl[2 * pi][1] = tmp[1];
                bl[2 * pi + 1][0] = tmp[2]; bl[2 * pi + 1][1] = tmp[3];
            }
            #pragma unroll
            for (int mi = 0; mi < 4; mi++)
                #pragma unroll
                for (int ni = 0; ni < 4; ni++) {
                    mma_bf16(c[mi][ni], ah[mi], bh[ni]);
                    mma_bf16(c[mi][ni], ah[mi], bl[ni]);
                    mma_bf16(c[mi][ni], al[mi], bh[ni]);
                }
        }
        buf = (buf == 2) ? 0 : buf + 1;
        nbuf = (nbuf == 2) ? 0 : nbuf + 1;
    }

    // epilogue
    if (which < 3) {
        const int bidx = m0 >> 10;
        #pragma unroll
        for (int mi = 0; mi < 4; mi++) {
            #pragma unroll
            for (int r = 0; r < 2; r++) {
                int m = m0 + wm * 64 + mi * 16 + gid + r * 8;
                int t = m & 1023;
                #pragma unroll
                for (int ni = 0; ni < 4; ni++) {
                    int nb = n0 + wn * 32 + ni * 8 + 2 * tig;
                    float v0 = c[mi][ni][r * 2 + 0] + bias[nb];
                    float v1 = c[mi][ni][r * 2 + 1] + bias[nb + 1];
                    Out[(((size_t)(bidx << 10) + nb) << 10) + t] = v0;
                    Out[(((size_t)(bidx << 10) + nb + 1) << 10) + t] = v1;
                }
            }
        }
    } else {
        #pragma unroll
        for (int mi = 0; mi < 4; mi++) {
            #pragma unroll
            for (int r = 0; r < 2; r++) {
                int m = m0 + wm * 64 + mi * 16 + gid + r * 8;
                #pragma unroll
                for (int ni = 0; ni < 4; ni++) {
                    int nb = n0 + wn * 32 + ni * 8 + 2 * tig;
                    float2 v;
                    v.x = c[mi][ni][r * 2 + 0] + bias[nb];
                    v.y = c[mi][ni][r * 2 + 1] + bias[nb + 1];
                    *(float2*)&Out[(size_t)m * 1024 + nb] = v;
                }
            }
        }
    }
}

// ---------------- radix-4 DIF FFT + cross spectrum --------------------------
__device__ __forceinline__ int fswz(int p) { return p ^ ((p >> 2) & 15); }
__device__ __forceinline__ int rev4(int x) {
    return ((x & 3) << 8) | (((x >> 2) & 3) << 6) | (((x >> 4) & 3) << 4)
         | (((x >> 6) & 3) << 2) | ((x >> 8) & 3);
}
__device__ __forceinline__ float2 cmul(float2 a, float2 w) {
    return make_float2(a.x * w.x - a.y * w.y, a.x * w.y + a.y * w.x);
}

__global__ void __launch_bounds__(256) fft_corr_kernel()
{
    __shared__ float2 Zs[1024];
    __shared__ float2 tw[1024];
    const int row = blockIdx.x;
    const int t = threadIdx.x;
    const float* qr = g_q + (size_t)row * 1024;
    const float* kr = g_k + (size_t)row * 1024;

    for (int j = t; j < 1024; j += 256) {
        float s, c;
        sincospif(-(float)j / 512.0f, &s, &c);
        tw[j] = make_float2(c, s);
    }
    __syncthreads();

    {
        float2 x0 = make_float2(qr[t],       kr[t]);
        float2 x1 = make_float2(qr[t + 256], kr[t + 256]);
        float2 x2 = make_float2(qr[t + 512], kr[t + 512]);
        float2 x3 = make_float2(qr[t + 768], kr[t + 768]);
        float2 p02 = make_float2(x0.x + x2.x, x0.y + x2.y);
        float2 m02 = make_float2(x0.x - x2.x, x0.y - x2.y);
        float2 p13 = make_float2(x1.x + x3.x, x1.y + x3.y);
        float2 m13 = make_float2(x1.x - x3.x, x1.y - x3.y);
        float2 y0 = make_float2(p02.x + p13.x, p02.y + p13.y);
        float2 y2 = make_float2(p02.x - p13.x, p02.y - p13.y);
        float2 y1 = make_float2(m02.x + m13.y, m02.y - m13.x);
        float2 y3 = make_float2(m02.x - m13.y, m02.y + m13.x);
        int e = t;
        Zs[fswz(t)]       = y0;
        Zs[fswz(t + 256)] = cmul(y1, tw[e]);
        Zs[fswz(t + 512)] = cmul(y2, tw[2 * e]);
        Zs[fswz(t + 768)] = cmul(y3, tw[3 * e]);
    }
    __syncthreads();

    #pragma unroll
    for (int s = 1; s < 5; s++) {
        const int qsh = 8 - 2 * s;
        const int quarter = 1 << qsh;
        const int j = t & (quarter - 1);
        const int i0 = ((t >> qsh) << (qsh + 2)) + j;
        const int e = j << (2 * s);
        float2 x0 = Zs[fswz(i0)];
        float2 x1 = Zs[fswz(i0 + quarter)];
        float2 x2 = Zs[fswz(i0 + 2 * quarter)];
        float2 x3 = Zs[fswz(i0 + 3 * quarter)];
        float2 p02 = make_float2(x0.x + x2.x, x0.y + x2.y);
        float2 m02 = make_float2(x0.x - x2.x, x0.y - x2.y);
        float2 p13 = make_float2(x1.x + x3.x, x1.y + x3.y);
        float2 m13 = make_float2(x1.x - x3.x, x1.y - x3.y);
        float2 y0 = make_float2(p02.x + p13.x, p02.y + p13.y);
        float2 y2 = make_float2(p02.x - p13.x, p02.y - p13.y);
        float2 y1 = make_float2(m02.x + m13.y, m02.y - m13.x);
        float2 y3 = make_float2(m02.x - m13.y, m02.y + m13.x);
        __syncthreads();
        Zs[fswz(i0)]               = y0;
        Zs[fswz(i0 + quarter)]     = cmul(y1, tw[e]);
        Zs[fswz(i0 + 2 * quarter)] = cmul(y2, tw[2 * e]);
        Zs[fswz(i0 + 3 * quarter)] = cmul(y3, tw[3 * e]);
        __syncthreads();
    }

    for (int f = F0 + t; f <= 512; f += 256) {
        float2 A  = Zs[fswz(rev4(f))];
        float2 Zc = Zs[fswz(rev4(1024 - f))];
        float Br =  Zc.x, Bi = -Zc.y;
        float Ur = A.x + Br, Ui = A.y + Bi;
        float Vr = A.x - Br, Vi = A.y - Bi;
        float Pr = 0.25f * (Ur * Vi - Ui * Vr);
        float Pi = 0.25f * (Ur * Vr + Ui * Vi);
        g_P[(size_t)row * NF + (f - F0)] = make_float2(Pr, Pi);
    }
}

// ---------------- deterministic channel reduction ---------------------------
__global__ void __launch_bounds__(256) reduce_S_kernel()
{
    const int b = blockIdx.x, j = blockIdx.y;
    const int tid = threadIdx.x;
    float2 acc = make_float2(0.f, 0.f);
    for (int r = tid; r < 1024; r += 256) {
        float2 p = g_P[(size_t)((b << 10) + r) * NF + j];
        acc.x += p.x; acc.y += p.y;
    }
    __shared__ float2 sh[256];
    sh[tid] = acc;
    __syncthreads();
    for (int o = 128; o > 0; o >>= 1) {
        if (tid < o) { sh[tid].x += sh[tid + o].x; sh[tid].y += sh[tid + o].y; }
        __syncthreads();
    }
    if (tid == 0) g_S[b][j] = sh[0];
}

// ---------------- irfft of masked spectrum -> mean_value --------------------
__global__ void __launch_bounds__(256) irfft_mean_kernel()
{
    __shared__ float2 tw[1024];
    __shared__ float2 Sb[NF];
    const int b = blockIdx.x;
    const int tid = threadIdx.x;
    for (int j = tid; j < 1024; j += 256) {
        float s, c;
        sincospif((float)j / 512.0f, &s, &c);
        tw[j] = make_float2(c, s);
    }
    for (int j = tid; j < NF; j += 256) Sb[j] = g_S[b][j];
    __syncthreads();

    const int tau = blockIdx.y * 256 + tid;
    float acc = 0.f;
    #pragma unroll 4
    for (int j = 0; j < NF - 1; j++) {
        int id = ((F0 + j) * tau) & 1023;
        float2 s = Sb[j], w = tw[id];
        acc += s.x * w.x - s.y * w.y;
    }
    acc *= 2.0f;
    {
        int id = (512 * tau) & 1023;
        float2 s = Sb[NF - 1], w = tw[id];
        acc += s.x * w.x - s.y * w.y;
    }
    g_mv[b][tau] = acc * (1.0f / (1024.0f * 1024.0f));
}

// ---------------- global top-6 lags + per-batch softmax ---------------------
__global__ void __launch_bounds__(256) topk_kernel()
{
    __shared__ float g[1024];
    __shared__ float rv[256];
    __shared__ int   ri[256];
    __shared__ int   chosen[TOPK];
    const int tid = threadIdx.x;

    for (int t = tid; t < 1024; t += 256) {
        float s = 0.f;
        #pragma unroll
        for (int b = 0; b < BB; b++) s += g_mv[b][t];
        g[t] = s;
    }
    __syncthreads();

    for (int p = 0; p < TOPK; p++) {
        float best = -3.0e38f; int bi = 1 << 30;
        for (int t = tid; t < 1024; t += 256) {
            float v = g[t];
            if (v > best) { best = v; bi = t; }
        }
        rv[tid] = best; ri[tid] = bi;
        __syncthreads();
        for (int o = 128; o > 0; o >>= 1) {
            if (tid < o) {
                float v2 = rv[tid + o]; int i2 = ri[tid + o];
                if (v2 > rv[tid] || (v2 == rv[tid] && i2 < ri[tid])) {
                    rv[tid] = v2; ri[tid] = i2;
                }
            }
            __syncthreads();
        }
        if (tid == 0) { chosen[p] = ri[0]; g[ri[0]] = -3.0e38f; }
        __syncthreads();
    }

    if (tid < BB) {
        int b = tid;
        float w[TOPK], mx = -3.0e38f;
        #pragma unroll
        for (int i = 0; i < TOPK; i++) { w[i] = g_mv[b][chosen[i]]; mx = fmaxf(mx, w[i]); }
        float sum = 0.f;
        #pragma unroll
        for (int i = 0; i < TOPK; i++) { w[i] = expf(w[i] - mx); sum += w[i]; }
        #pragma unroll
        for (int i = 0; i < TOPK; i++) g_tc[b][i] = w[i] / sum;
    }
    if (tid >= 32 && tid < 32 + TOPK) g_idx[tid - 32] = chosen[tid - 32];
}

// ---------------- fused shift-agg + transpose + bf16 split ------------------
#define GT_SMEM (32 * 1025 * 4)
__global__ void __launch_bounds__(256) gatherT_kernel()
{
    extern __shared__ float vs[];            // [32][1025]
    __shared__ int   sh[TOPK];
    __shared__ float w[TOPK];
    const int b  = blockIdx.y;
    const int c0 = blockIdx.x * 32;
    const int tid = threadIdx.x;
    if (tid < TOPK) { sh[tid] = g_idx[tid]; w[tid] = g_tc[b][tid]; }
    for (int idx = tid; idx < 32 * 1024; idx += 256) {
        int r = idx >> 10, t = idx & 1023;
        vs[r * 1025 + t] = g_v[((size_t)(b << 10) + c0 + r) * 1024 + t];
    }
    __syncthreads();
    const int cc = tid & 31;
    for (int tt = tid >> 5; tt < 1024; tt += 8) {
        float a = 0.f;
        #pragma unroll
        for (int i = 0; i < TOPK; i++)
            a += w[i] * vs[cc * 1025 + ((tt + sh[i]) & 1023)];
        size_t pos = ((size_t)(b << 10) + tt) * 1024 + c0 + cc;
        __nv_bfloat16 h, l;
        split1(a, h, l);
        g_ctx_hi[pos] = h;
        g_ctx_lo[pos] = l;
    }
}

// ---------------- residual + LayerNorm --------------------------------------
__global__ void __launch_bounds__(256) ln_kernel(
    const float* __restrict__ x, const float* __restrict__ gamma,
    const float* __restrict__ beta, float* __restrict__ out)
{
    const int m = blockIdx.x;
    const int tid = threadIdx.x;
    const float* h  = g_hidden + (size_t)m * 1024;
    const float* xi = x        + (size_t)m * 1024;

    float v[4];
    float s1 = 0.f, s2 = 0.f;
    #pragma unroll
    for (int i = 0; i < 4; i++) {
        float t = h[tid + 256 * i] + xi[tid + 256 * i];
        v[i] = t; s1 += t; s2 += t * t;
    }
    #pragma unroll
    for (int o = 16; o > 0; o >>= 1) {
        s1 += __shfl_xor_sync(0xffffffffu, s1, o);
        s2 += __shfl_xor_sync(0xffffffffu, s2, o);
    }
    __shared__ float w1[8], w2[8];
    __shared__ float sh_mean, sh_inv;
    const int wid = tid >> 5, lane = tid & 31;
    if (lane == 0) { w1[wid] = s1; w2[wid] = s2; }
    __syncthreads();
    if (tid == 0) {
        float a = 0.f, bq = 0.f;
        #pragma unroll
        for (int i = 0; i < 8; i++) { a += w1[i]; bq += w2[i]; }
        float mean = a * (1.0f / 1024.0f);
        float var  = bq * (1.0f / 1024.0f) - mean * mean;
        sh_mean = mean;
        sh_inv  = rsqrtf(var + 1e-12f);
    }
    __syncthreads();
    const float mean = sh_mean, inv = sh_inv;
    #pragma unroll
    for (int i = 0; i < 4; i++) {
        int c = tid + 256 * i;
        out[(size_t)m * 1024 + c] = (v[i] - mean) * inv * gamma[c] + beta[c];
    }
}

// ---------------- launch ----------------------------------------------------
extern "C" void kernel_launch(void* const* d_in, const int* in_sizes, int n_in,
                              void* d_out, int out_size)
{
    (void)in_sizes; (void)n_in; (void)out_size;
    const float* x     = (const float*)d_in[0];
    const float* Wq    = (const float*)d_in[2];
    const float* bq    = (const float*)d_in[3];
    const float* Wk    = (const float*)d_in[4];
    const float* bk    = (const float*)d_in[5];
    const float* Wv    = (const float*)d_in[6];
    const float* bv    = (const float*)d_in[7];
    const float* Wd    = (const float*)d_in[8];
    const float* bd    = (const float*)d_in[9];
    const float* gamma = (const float*)d_in[10];
    const float* beta  = (const float*)d_in[11];
    float* out = (float*)d_out;

    static cudaStream_t s2 = nullptr;
    static cudaEvent_t ev0 = nullptr, evT = nullptr, evQK = nullptr, evV = nullptr;
    static bool attr_done = false;
    if (!attr_done) {
        cudaFuncSetAttribute(gemm_bf16,      cudaFuncAttributeMaxDynamicSharedMemorySize, GSMEM);
        cudaFuncSetAttribute(gatherT_kernel, cudaFuncAttributeMaxDynamicSharedMemorySize, GT_SMEM);
        cudaStreamCreateWithFlags(&s2, cudaStreamNonBlocking);
        cudaEventCreateWithFlags(&ev0,  cudaEventDisableTiming);
        cudaEventCreateWithFlags(&evT,  cudaEventDisableTiming);
        cudaEventCreateWithFlags(&evQK, cudaEventDisableTiming);
        cudaEventCreateWithFlags(&evV,  cudaEventDisableTiming);
        attr_done = true;
    }

    // fork: transpose_w on s2 runs concurrently with split_x on main
    cudaEventRecord(ev0, 0);
    cudaStreamWaitEvent(s2, ev0, 0);
    transpose_w<<<dim3(32, 32, 4), 256, 0, s2>>>(Wq, Wk, Wv, Wd);
    split_x_kernel<<<NROW * LL / 1024, 256>>>(x);
    cudaEventRecord(evT, s2);
    cudaStreamWaitEvent(0, evT, 0);

    // Q,K GEMM on main stream (needs x split + weights)
    gemm_bf16<<<dim3(8, 128, 2), 256, GSMEM>>>(bq, bk, bv, 0);
    cudaEventRecord(evQK, 0);

    // V GEMM on s2, concurrent with the FFT chain on main
    cudaStreamWaitEvent(s2, evQK, 0);
    gemm_bf16<<<dim3(8, 128, 1), 256, GSMEM, s2>>>(bq, bk, bv, 2);
    cudaEventRecord(evV, s2);

    fft_corr_kernel<<<NROW, 256>>>();
    reduce_S_kernel<<<dim3(BB, NF), 256>>>();
    irfft_mean_kernel<<<dim3(BB, 4), 256>>>();
    topk_kernel<<<1, 256>>>();

    // join: gatherT needs both topk (main) and v (s2)
    cudaStreamWaitEvent(0, evV, 0);
    gatherT_kernel<<<dim3(32, BB), 256, GT_SMEM>>>();
    gemm_bf16<<<dim3(8, 128, 1), 256, GSMEM>>>(bd, bd, bd, 3);
    ln_kernel<<<NROW, 256>>>(x, gamma, beta, out);
}